// round 2
// baseline (speedup 1.0000x reference)
#include <cuda_runtime.h>
#include <cstdint>
#include <math.h>

#define B_    8192
#define DIN_  1024
#define DH_   2048
#define DOUT_ 1024
#define NE_   8
#define TAU_  0.8f
#define LAMB_ 0.05f

#define BM 128
#define BN 128
#define BK 32
#define ALD 36    // A smem row stride (floats): conflict-free frag loads, float4-aligned
#define BLD 136   // B smem row stride (floats): conflict-free frag loads, float4-aligned

// -------- scratch (no allocs allowed; __device__ globals) --------
__device__ float g_probs[(size_t)B_ * NE_];
__device__ float g_sums[16];                         // [0..7] sum probs col, [8..15] sum router col
__device__ float g_hprime[(size_t)B_ * NE_ * DH_];   // 512 MB: h' = probs * relu(x@w1+b1), [B][E*Dh]

// ---------------- helpers ----------------
__device__ __forceinline__ float to_tf32(float v) {
    uint32_t u;
    asm("cvt.rna.tf32.f32 %0, %1;" : "=r"(u) : "f"(v));
    return __uint_as_float(u);
}

__device__ __forceinline__ void mma8(float* c, const uint32_t* a, const uint32_t* b) {
    asm volatile(
        "mma.sync.aligned.m16n8k8.row.col.f32.tf32.tf32.f32 "
        "{%0,%1,%2,%3},{%4,%5,%6,%7},{%8,%9},{%0,%1,%2,%3};"
        : "+f"(c[0]), "+f"(c[1]), "+f"(c[2]), "+f"(c[3])
        : "r"(a[0]), "r"(a[1]), "r"(a[2]), "r"(a[3]), "r"(b[0]), "r"(b[1]));
}

__device__ __forceinline__ void sts_tiles(float* As, float* Bs, int buf,
                                          const float4* ar, const float4* br, int tid) {
#pragma unroll
    for (int i = 0; i < 4; i++) {
        int id = tid + i * 256;
        int m = id >> 3, kv = (id & 7) << 2;
        float4 v;
        v.x = to_tf32(ar[i].x); v.y = to_tf32(ar[i].y);
        v.z = to_tf32(ar[i].z); v.w = to_tf32(ar[i].w);
        *(float4*)(As + (size_t)buf * (BM * ALD) + m * ALD + kv) = v;
        int k = id >> 5, nv = (id & 31) << 2;
        float4 w;
        w.x = to_tf32(br[i].x); w.y = to_tf32(br[i].y);
        w.z = to_tf32(br[i].z); w.w = to_tf32(br[i].w);
        *(float4*)(Bs + (size_t)buf * (BK * BLD) + k * BLD + nv) = w;
    }
}

// Double-buffered 128x128x32 tf32 GEMM core. A row-major [.,LDA], B row-major [K,LDB].
template <int KT, int LDA, int LDB>
__device__ __forceinline__ void gemm_core(const float* __restrict__ A,
                                          const float* __restrict__ Bp,
                                          float* As, float* Bs,
                                          float acc[4][4][4]) {
    const int tid  = threadIdx.x;
    const int lane = tid & 31, warp = tid >> 5;
    const int g = lane >> 2, t = lane & 3;
    const int wm = warp >> 2, wn = warp & 3;  // 2x4 warp grid, warp tile 64x32

    float4 ar[4], br[4];
#pragma unroll
    for (int i = 0; i < 4; i++) {
        int id = tid + i * 256;
        int m = id >> 3, kv = (id & 7) << 2;
        ar[i] = *(const float4*)(A + (size_t)m * LDA + kv);
        int k = id >> 5, nv = (id & 31) << 2;
        br[i] = *(const float4*)(Bp + (size_t)k * LDB + nv);
    }
    sts_tiles(As, Bs, 0, ar, br, tid);
    __syncthreads();

    int cur = 0;
    for (int kt = 0; kt < KT; kt++) {
        if (kt + 1 < KT) {
#pragma unroll
            for (int i = 0; i < 4; i++) {
                int id = tid + i * 256;
                int m = id >> 3, kv = (id & 7) << 2;
                ar[i] = *(const float4*)(A + (size_t)m * LDA + (kt + 1) * BK + kv);
                int k = id >> 5, nv = (id & 31) << 2;
                br[i] = *(const float4*)(Bp + (size_t)((kt + 1) * BK + k) * LDB + nv);
            }
        }
        const float* Ab = As + (size_t)cur * (BM * ALD);
        const float* Bb = Bs + (size_t)cur * (BK * BLD);
#pragma unroll
        for (int ks = 0; ks < 4; ks++) {
            uint32_t af[4][4], bf[4][2];
            int kk = ks * 8 + t;
#pragma unroll
            for (int mt = 0; mt < 4; mt++) {
                int m = wm * 64 + mt * 16 + g;
                af[mt][0] = __float_as_uint(Ab[m * ALD + kk]);
                af[mt][1] = __float_as_uint(Ab[(m + 8) * ALD + kk]);
                af[mt][2] = __float_as_uint(Ab[m * ALD + kk + 4]);
                af[mt][3] = __float_as_uint(Ab[(m + 8) * ALD + kk + 4]);
            }
#pragma unroll
            for (int nt = 0; nt < 4; nt++) {
                int n = wn * 32 + nt * 8 + g;
                bf[nt][0] = __float_as_uint(Bb[kk * BLD + n]);
                bf[nt][1] = __float_as_uint(Bb[(kk + 4) * BLD + n]);
            }
#pragma unroll
            for (int mt = 0; mt < 4; mt++)
#pragma unroll
                for (int nt = 0; nt < 4; nt++)
                    mma8(acc[mt][nt], af[mt], bf[nt]);
        }
        if (kt + 1 < KT) {
            sts_tiles(As, Bs, cur ^ 1, ar, br, tid);
            __syncthreads();
            cur ^= 1;
        }
    }
}

// ---------------- kernels ----------------
__global__ void zero_kernel() {
    if (threadIdx.x < 16) g_sums[threadIdx.x] = 0.f;
}

// logits, gumbel-softmax probs, router softmax, column-sum accumulation
__global__ __launch_bounds__(256) void gate_kernel(const float* __restrict__ x,
                                                   const float* __restrict__ gum,
                                                   const float* __restrict__ gw,
                                                   const float* __restrict__ gb) {
    __shared__ float psum[16];
    int tid = threadIdx.x;
    if (tid < 16) psum[tid] = 0.f;
    __syncthreads();
    int warp = tid >> 5, lane = tid & 31;
    int row = blockIdx.x * 8 + warp;

    float acc[NE_];
#pragma unroll
    for (int e = 0; e < NE_; e++) acc[e] = 0.f;
    const float* xr = x + (size_t)row * DIN_;
    for (int k = lane; k < DIN_; k += 32) {
        float xv = xr[k];
        float4 w0 = *(const float4*)(gw + (size_t)k * NE_);
        float4 w1v = *(const float4*)(gw + (size_t)k * NE_ + 4);
        acc[0] += xv * w0.x;  acc[1] += xv * w0.y;
        acc[2] += xv * w0.z;  acc[3] += xv * w0.w;
        acc[4] += xv * w1v.x; acc[5] += xv * w1v.y;
        acc[6] += xv * w1v.z; acc[7] += xv * w1v.w;
    }
#pragma unroll
    for (int e = 0; e < NE_; e++) {
#pragma unroll
        for (int off = 16; off > 0; off >>= 1)
            acc[e] += __shfl_xor_sync(0xffffffffu, acc[e], off);
    }
    if (lane == 0) {
        float s1[NE_], s2[NE_];
        float m1 = -1e30f, m2 = -1e30f;
#pragma unroll
        for (int e = 0; e < NE_; e++) {
            float lg = acc[e] + gb[e];
            s1[e] = (lg + gum[(size_t)row * NE_ + e]) * (1.0f / TAU_);
            s2[e] = lg * (1.0f / TAU_);
            m1 = fmaxf(m1, s1[e]); m2 = fmaxf(m2, s2[e]);
        }
        float d1 = 0.f, d2 = 0.f;
#pragma unroll
        for (int e = 0; e < NE_; e++) {
            s1[e] = expf(s1[e] - m1); s2[e] = expf(s2[e] - m2);
            d1 += s1[e]; d2 += s2[e];
        }
#pragma unroll
        for (int e = 0; e < NE_; e++) {
            float p = s1[e] / d1, r = s2[e] / d2;
            g_probs[(size_t)row * NE_ + e] = p;
            atomicAdd(&psum[e], p);
            atomicAdd(&psum[8 + e], r);
        }
    }
    __syncthreads();
    if (tid < 16) atomicAdd(&g_sums[tid], psum[tid]);
}

// h'[b, e*Dh + n] = probs[b,e] * relu(x @ w1[e] + b1[e])
__global__ __launch_bounds__(256) void gemm1_kernel(const float* __restrict__ x,
                                                    const float* __restrict__ w1,
                                                    const float* __restrict__ b1) {
    extern __shared__ float smem[];
    float* As = smem;
    float* Bs = smem + 2 * BM * ALD;
    float* bias_s  = Bs + 2 * BK * BLD;   // [BN]
    float* probs_s = bias_s + BN;         // [BM]

    const int e  = blockIdx.z;
    const int m0 = blockIdx.y * BM;
    const int n0 = blockIdx.x * BN;
    const int tid = threadIdx.x;

    for (int i = tid; i < BN; i += 256) bias_s[i]  = b1[e * DH_ + n0 + i];
    for (int i = tid; i < BM; i += 256) probs_s[i] = g_probs[(size_t)(m0 + i) * NE_ + e];

    float acc[4][4][4];
#pragma unroll
    for (int a = 0; a < 4; a++)
#pragma unroll
        for (int b = 0; b < 4; b++)
#pragma unroll
            for (int c = 0; c < 4; c++) acc[a][b][c] = 0.f;

    gemm_core<DIN_ / BK, DIN_, DH_>(x + (size_t)m0 * DIN_,
                                    w1 + (size_t)e * DIN_ * DH_ + n0,
                                    As, Bs, acc);

    const int lane = tid & 31, warp = tid >> 5;
    const int g = lane >> 2, t = lane & 3, wm = warp >> 2, wn = warp & 3;
#pragma unroll
    for (int mt = 0; mt < 4; mt++) {
#pragma unroll
        for (int nt = 0; nt < 4; nt++) {
            int r0 = wm * 64 + mt * 16 + g;
            int c0 = wn * 32 + nt * 8 + 2 * t;
#pragma unroll
            for (int h = 0; h < 2; h++) {
                int r = r0 + h * 8;
                float p = probs_s[r];
                float2 v;
                v.x = p * fmaxf(acc[mt][nt][2 * h + 0] + bias_s[c0], 0.f);
                v.y = p * fmaxf(acc[mt][nt][2 * h + 1] + bias_s[c0 + 1], 0.f);
                size_t idx = (size_t)(m0 + r) * (NE_ * DH_) + (size_t)e * DH_ + n0 + c0;
                *(float2*)(g_hprime + idx) = v;
            }
        }
    }
}

// out = h' @ w2_flat + sum_e probs[:,e]*b2[e,:]
__global__ __launch_bounds__(256) void gemm2_kernel(const float* __restrict__ w2,
                                                    const float* __restrict__ b2,
                                                    float* __restrict__ out) {
    extern __shared__ float smem[];
    float* As  = smem;
    float* Bs  = smem + 2 * BM * ALD;
    float* b2s = Bs + 2 * BK * BLD;   // [NE_][BN]
    float* ps  = b2s + NE_ * BN;      // [BM][NE_]

    const int m0 = blockIdx.y * BM;
    const int n0 = blockIdx.x * BN;
    const int tid = threadIdx.x;

    for (int i = tid; i < NE_ * BN; i += 256) {
        int e = i / BN, c = i % BN;
        b2s[i] = b2[e * DOUT_ + n0 + c];
    }
    for (int i = tid; i < BM * NE_; i += 256)
        ps[i] = g_probs[(size_t)m0 * NE_ + i];

    float acc[4][4][4];
#pragma unroll
    for (int a = 0; a < 4; a++)
#pragma unroll
        for (int b = 0; b < 4; b++)
#pragma unroll
            for (int c = 0; c < 4; c++) acc[a][b][c] = 0.f;

    gemm_core<(NE_ * DH_) / BK, NE_ * DH_, DOUT_>(g_hprime + (size_t)m0 * (NE_ * DH_),
                                                  w2 + n0, As, Bs, acc);

    const int lane = tid & 31, warp = tid >> 5;
    const int g = lane >> 2, t = lane & 3, wm = warp >> 2, wn = warp & 3;
#pragma unroll
    for (int mt = 0; mt < 4; mt++) {
#pragma unroll
        for (int nt = 0; nt < 4; nt++) {
            int r0 = wm * 64 + mt * 16 + g;
            int c0 = wn * 32 + nt * 8 + 2 * t;
#pragma unroll
            for (int h = 0; h < 2; h++) {
                int r = r0 + h * 8;
                float bias0 = 0.f, bias1 = 0.f;
#pragma unroll
                for (int e = 0; e < NE_; e++) {
                    float p = ps[r * NE_ + e];
                    bias0 += p * b2s[e * BN + c0];
                    bias1 += p * b2s[e * BN + c0 + 1];
                }
                float2 v;
                v.x = acc[mt][nt][2 * h + 0] + bias0;
                v.y = acc[mt][nt][2 * h + 1] + bias1;
                *(float2*)(out + (size_t)(m0 + r) * DOUT_ + n0 + c0) = v;
            }
        }
    }
}

__global__ void aux_kernel(float* __restrict__ out, int out_size) {
    if (threadIdx.x != 0 || blockIdx.x != 0) return;
    float ld[NE_], imp[NE_];
    float sl = 0.f, si = 0.f;
#pragma unroll
    for (int e = 0; e < NE_; e++) {
        ld[e]  = g_sums[e] / (float)B_;
        imp[e] = g_sums[8 + e] / (float)B_;
        sl += ld[e]; si += imp[e];
    }
    float ml = sl / (float)NE_, mi = si / (float)NE_;
    float vl = 0.f, vi = 0.f, sw = 0.f;
#pragma unroll
    for (int e = 0; e < NE_; e++) {
        vl += (ld[e] - ml) * (ld[e] - ml);
        vi += (imp[e] - mi) * (imp[e] - mi);
        sw += imp[e] * ld[e];
    }
    float cvl = sqrtf(vl / (float)(NE_ - 1)) / (ml + 1e-8f);
    float cvi = sqrtf(vi / (float)(NE_ - 1)) / (mi + 1e-8f);
    out[out_size - 1] = ((float)NE_ * sw + cvi + cvl) * LAMB_;
}

// ---------------- launch ----------------
extern "C" void kernel_launch(void* const* d_in, const int* in_sizes, int n_in,
                              void* d_out, int out_size) {
    const float* x   = (const float*)d_in[0];
    const float* gum = (const float*)d_in[1];
    const float* gw  = (const float*)d_in[2];
    const float* gb  = (const float*)d_in[3];
    const float* w1  = (const float*)d_in[4];
    const float* b1  = (const float*)d_in[5];
    const float* w2  = (const float*)d_in[6];
    const float* b2  = (const float*)d_in[7];
    float* out = (float*)d_out;

    const int SMEM_CORE = (2 * BM * ALD + 2 * BK * BLD) * 4;
    const int SMEM1 = SMEM_CORE + (BN + BM) * 4;
    const int SMEM2 = SMEM_CORE + (NE_ * BN + BM * NE_) * 4;
    cudaFuncSetAttribute((const void*)gemm1_kernel,
                         cudaFuncAttributeMaxDynamicSharedMemorySize, SMEM1);
    cudaFuncSetAttribute((const void*)gemm2_kernel,
                         cudaFuncAttributeMaxDynamicSharedMemorySize, SMEM2);

    zero_kernel<<<1, 32>>>();
    gate_kernel<<<B_ / 8, 256>>>(x, gum, gw, gb);
    gemm1_kernel<<<dim3(DH_ / BN, B_ / BM, NE_), 256, SMEM1>>>(x, w1, b1);
    gemm2_kernel<<<dim3(DOUT_ / BN, B_ / BM), 256, SMEM2>>>(w2, b2, out);
    aux_kernel<<<1, 1>>>(out, out_size);
}

// round 5
// speedup vs baseline: 1.4926x; 1.4926x over previous
#include <cuda_runtime.h>
#include <cstdint>
#include <math.h>

#define B_    8192
#define DIN_  1024
#define DH_   2048
#define DOUT_ 1024
#define NE_   8
#define TAU_  0.8f
#define LAMB_ 0.05f

// block 128x256, 8 warps (2x4), warp tile 64x64, BK=32, 4 cp.async stages
#define BM 128
#define BN 256
#define BK 32
#define STAGES 4
#define A_STG (BM * BK)             // 4096 floats (ALD=32, XOR swizzle)
#define B_STG (BK * BN)             // 8192 floats (BLD=256, XOR swizzle)
#define STG_F (A_STG + B_STG)       // 12288 floats / stage
#define SMEM_BYTES (STAGES * STG_F * 4 + NE_ * BN * 4)

// -------- scratch (__device__ globals; no allocs allowed) --------
__device__ float g_probs[(size_t)B_ * NE_];
__device__ float g_sums[16];
__device__ float g_hprime[(size_t)B_ * NE_ * DH_];   // tf32-rounded h'
__device__ float g_xr[(size_t)B_ * DIN_];
__device__ float g_w1r[(size_t)NE_ * DIN_ * DH_];
__device__ float g_w2r[(size_t)NE_ * DH_ * DOUT_];

// ---------------- helpers ----------------
__device__ __forceinline__ uint32_t smem_u32(const void* p) {
    uint32_t a;
    asm("{ .reg .u64 t; cvta.to.shared.u64 t, %1; cvt.u32.u64 %0, t; }" : "=r"(a) : "l"(p));
    return a;
}
__device__ __forceinline__ float to_tf32(float v) {
    uint32_t u;
    asm("cvt.rna.tf32.f32 %0, %1;" : "=r"(u) : "f"(v));
    return __uint_as_float(u);
}
__device__ __forceinline__ void cpa16(uint32_t dst, const void* src) {
    asm volatile("cp.async.cg.shared.global [%0], [%1], 16;" :: "r"(dst), "l"(src));
}
#define CP_COMMIT() asm volatile("cp.async.commit_group;" ::: "memory")
#define CP_WAIT2()  asm volatile("cp.async.wait_group 2;" ::: "memory")

__device__ __forceinline__ void mma8(float* c, const uint32_t* a, const uint32_t* b) {
    asm volatile(
        "mma.sync.aligned.m16n8k8.row.col.f32.tf32.tf32.f32 "
        "{%0,%1,%2,%3},{%4,%5,%6,%7},{%8,%9},{%0,%1,%2,%3};"
        : "+f"(c[0]), "+f"(c[1]), "+f"(c[2]), "+f"(c[3])
        : "r"(a[0]), "r"(a[1]), "r"(a[2]), "r"(a[3]), "r"(b[0]), "r"(b[1]));
}

// ---------------- prep: tf32 rounding pass ----------------
__global__ __launch_bounds__(256) void round_kernel(const float* __restrict__ src,
                                                    float* __restrict__ dst, int n4) {
    int stride = gridDim.x * 256;
    for (int i = blockIdx.x * 256 + threadIdx.x; i < n4; i += stride) {
        float4 v = ((const float4*)src)[i];
        v.x = to_tf32(v.x); v.y = to_tf32(v.y);
        v.z = to_tf32(v.z); v.w = to_tf32(v.w);
        ((float4*)dst)[i] = v;
    }
}

// ---------------- main GEMM ----------------
// MODE 1: h' = tf32(probs * relu(xr @ w1r + b1)), grid.z = expert
// MODE 2: out = h' @ w2r_flat + sum_e probs*b2
template <int MODE>
__global__ __launch_bounds__(256) void gemm_cp(const float* __restrict__ Aglob,
                                               const float* __restrict__ Bglob,
                                               const float* __restrict__ bias,
                                               float* __restrict__ outp) {
    constexpr int KT  = (MODE == 1) ? (DIN_ / BK) : ((NE_ * DH_) / BK);
    constexpr int LDA = (MODE == 1) ? DIN_ : (NE_ * DH_);
    constexpr int LDB = (MODE == 1) ? DH_ : DOUT_;

    extern __shared__ float sm[];
    const int tid  = threadIdx.x;
    const int lane = tid & 31, warp = tid >> 5;
    const int g = lane >> 2, t = lane & 3;
    const int wm = warp >> 2, wn = warp & 3;     // 2x4 warps, warp tile 64x64

    const int e  = (MODE == 1) ? blockIdx.z : 0;
    const int m0 = blockIdx.y * BM;
    const int n0 = blockIdx.x * BN;
    const float* Ap = (MODE == 1) ? (Aglob + (size_t)m0 * LDA)
                                  : (g_hprime + (size_t)m0 * LDA);
    const float* Bp = (MODE == 1) ? (Bglob + (size_t)e * DIN_ * DH_ + n0)
                                  : (Bglob + n0);
    const uint32_t sbase = smem_u32(sm);

    if (MODE == 2) {
        for (int i = tid; i < NE_ * BN; i += 256) {
            int ee = i >> 8, c = i & 255;
            sm[STAGES * STG_F + i] = bias[(size_t)ee * DOUT_ + n0 + c];
        }
    }

    // async stage issuer: A phys = m*32 + (k ^ ((m&7)<<2)); B phys = k*256 + (n ^ ((k&3)<<3))
    auto issue = [&](int kt) {
        uint32_t as = sbase + (uint32_t)(kt & 3) * (STG_F * 4);
        uint32_t bs = as + A_STG * 4;
#pragma unroll
        for (int j = 0; j < 4; j++) {
            int id = tid + j * 256, m = id >> 3, kv = (id & 7) << 2;
            uint32_t off = (uint32_t)(m * 32 + (kv ^ ((m & 7) << 2)));
            cpa16(as + off * 4, Ap + (size_t)m * LDA + kt * BK + kv);
        }
#pragma unroll
        for (int j = 0; j < 8; j++) {
            int id = tid + j * 256, k = id >> 6, nv = (id & 63) << 2;
            uint32_t off = (uint32_t)(k * 256 + (nv ^ ((k & 3) << 3)));
            cpa16(bs + off * 4, Bp + (size_t)(kt * BK + k) * LDB + nv);
        }
    };

    float acc[4][8][4];
#pragma unroll
    for (int a = 0; a < 4; a++)
#pragma unroll
        for (int b = 0; b < 8; b++)
#pragma unroll
            for (int c = 0; c < 4; c++) acc[a][b][c] = 0.f;

    issue(0); CP_COMMIT();
    issue(1); CP_COMMIT();
    issue(2); CP_COMMIT();

    const int swa = g << 2;   // A xor term: (m&7)<<2 == g<<2 for all frag rows
    const int swb = t << 3;   // B xor term: (k&3)<<3 == t<<3 for kk and kk+4

    for (int kt = 0; kt < KT; kt++) {
        CP_WAIT2();
        __syncthreads();
        if (kt + 3 < KT) issue(kt + 3);
        CP_COMMIT();

        const float* As = sm + (size_t)(kt & 3) * STG_F;
        const float* Bs = As + A_STG;
#pragma unroll
        for (int ks = 0; ks < 4; ks++) {
            const int kk = ks * 8 + t;
            uint32_t af[4][4], bf[8][2];
#pragma unroll
            for (int mt = 0; mt < 4; mt++) {
                int m = wm * 64 + mt * 16 + g;
                af[mt][0] = __float_as_uint(As[m * 32 + (kk ^ swa)]);
                af[mt][1] = __float_as_uint(As[(m + 8) * 32 + (kk ^ swa)]);
                af[mt][2] = __float_as_uint(As[m * 32 + ((kk + 4) ^ swa)]);
                af[mt][3] = __float_as_uint(As[(m + 8) * 32 + ((kk + 4) ^ swa)]);
            }
#pragma unroll
            for (int nt = 0; nt < 8; nt++) {
                int n = wn * 64 + nt * 8 + g;
                bf[nt][0] = __float_as_uint(Bs[kk * 256 + (n ^ swb)]);
                bf[nt][1] = __float_as_uint(Bs[(kk + 4) * 256 + (n ^ swb)]);
            }
#pragma unroll
            for (int mt = 0; mt < 4; mt++)
#pragma unroll
                for (int nt = 0; nt < 8; nt++)
                    mma8(acc[mt][nt], af[mt], bf[nt]);
        }
    }
    __syncthreads();

    // ---------------- epilogue ----------------
#pragma unroll
    for (int mt = 0; mt < 4; mt++) {
        const int r0 = m0 + wm * 64 + mt * 16 + g;   // rows r0, r0+8
        float p0 = 0.f, p1 = 0.f;
        float pr0[NE_], pr1[NE_];
        if (MODE == 1) {
            p0 = g_probs[(size_t)r0 * NE_ + e];
            p1 = g_probs[(size_t)(r0 + 8) * NE_ + e];
        } else {
#pragma unroll
            for (int ee = 0; ee < NE_; ee++) {
                pr0[ee] = g_probs[(size_t)r0 * NE_ + ee];
                pr1[ee] = g_probs[(size_t)(r0 + 8) * NE_ + ee];
            }
        }
#pragma unroll
        for (int nt = 0; nt < 8; nt++) {
            const int c = wn * 64 + nt * 8 + 2 * t;
            if (MODE == 1) {
                float2 bv = *(const float2*)(bias + (size_t)e * DH_ + n0 + c);
                float2 v0, v1;
                v0.x = to_tf32(p0 * fmaxf(acc[mt][nt][0] + bv.x, 0.f));
                v0.y = to_tf32(p0 * fmaxf(acc[mt][nt][1] + bv.y, 0.f));
                v1.x = to_tf32(p1 * fmaxf(acc[mt][nt][2] + bv.x, 0.f));
                v1.y = to_tf32(p1 * fmaxf(acc[mt][nt][3] + bv.y, 0.f));
                size_t base = (size_t)e * DH_ + n0 + c;
                *(float2*)(g_hprime + (size_t)r0 * (NE_ * DH_) + base) = v0;
                *(float2*)(g_hprime + (size_t)(r0 + 8) * (NE_ * DH_) + base) = v1;
            } else {
                const float* b2s = sm + STAGES * STG_F;
                float bx0 = 0.f, by0 = 0.f, bx1 = 0.f, by1 = 0.f;
#pragma unroll
                for (int ee = 0; ee < NE_; ee++) {
                    float bx = b2s[ee * BN + c], by = b2s[ee * BN + c + 1];
                    bx0 += pr0[ee] * bx; by0 += pr0[ee] * by;
                    bx1 += pr1[ee] * bx; by1 += pr1[ee] * by;
                }
                float2 v0 = make_float2(acc[mt][nt][0] + bx0, acc[mt][nt][1] + by0);
                float2 v1 = make_float2(acc[mt][nt][2] + bx1, acc[mt][nt][3] + by1);
                *(float2*)(outp + (size_t)r0 * DOUT_ + n0 + c) = v0;
                *(float2*)(outp + (size_t)(r0 + 8) * DOUT_ + n0 + c) = v1;
            }
        }
    }
}

// ---------------- gating / aux ----------------
__global__ void zero_kernel() {
    if (threadIdx.x < 16) g_sums[threadIdx.x] = 0.f;
}

__global__ __launch_bounds__(256) void gate_kernel(const float* __restrict__ x,
                                                   const float* __restrict__ gum,
                                                   const float* __restrict__ gw,
                                                   const float* __restrict__ gb) {
    __shared__ float psum[16];
    int tid = threadIdx.x;
    if (tid < 16) psum[tid] = 0.f;
    __syncthreads();
    int warp = tid >> 5, lane = tid & 31;
    int row = blockIdx.x * 8 + warp;

    float acc[NE_];
#pragma unroll
    for (int e = 0; e < NE_; e++) acc[e] = 0.f;
    const float* xr = x + (size_t)row * DIN_;
    for (int k = lane; k < DIN_; k += 32) {
        float xv = xr[k];
        float4 w0 = *(const float4*)(gw + (size_t)k * NE_);
        float4 w1v = *(const float4*)(gw + (size_t)k * NE_ + 4);
        acc[0] += xv * w0.x;  acc[1] += xv * w0.y;
        acc[2] += xv * w0.z;  acc[3] += xv * w0.w;
        acc[4] += xv * w1v.x; acc[5] += xv * w1v.y;
        acc[6] += xv * w1v.z; acc[7] += xv * w1v.w;
    }
#pragma unroll
    for (int e = 0; e < NE_; e++) {
#pragma unroll
        for (int off = 16; off > 0; off >>= 1)
            acc[e] += __shfl_xor_sync(0xffffffffu, acc[e], off);
    }
    if (lane == 0) {
        float s1[NE_], s2[NE_];
        float m1 = -1e30f, m2 = -1e30f;
#pragma unroll
        for (int e = 0; e < NE_; e++) {
            float lg = acc[e] + gb[e];
            s1[e] = (lg + gum[(size_t)row * NE_ + e]) * (1.0f / TAU_);
            s2[e] = lg * (1.0f / TAU_);
            m1 = fmaxf(m1, s1[e]); m2 = fmaxf(m2, s2[e]);
        }
        float d1 = 0.f, d2 = 0.f;
#pragma unroll
        for (int e = 0; e < NE_; e++) {
            s1[e] = expf(s1[e] - m1); s2[e] = expf(s2[e] - m2);
            d1 += s1[e]; d2 += s2[e];
        }
#pragma unroll
        for (int e = 0; e < NE_; e++) {
            float p = s1[e] / d1, r = s2[e] / d2;
            g_probs[(size_t)row * NE_ + e] = p;
            atomicAdd(&psum[e], p);
            atomicAdd(&psum[8 + e], r);
        }
    }
    __syncthreads();
    if (tid < 16) atomicAdd(&g_sums[tid], psum[tid]);
}

__global__ void aux_kernel(float* __restrict__ out, int out_size) {
    if (threadIdx.x != 0 || blockIdx.x != 0) return;
    float ld[NE_], imp[NE_];
    float sl = 0.f, si = 0.f;
#pragma unroll
    for (int e = 0; e < NE_; e++) {
        ld[e]  = g_sums[e] / (float)B_;
        imp[e] = g_sums[8 + e] / (float)B_;
        sl += ld[e]; si += imp[e];
    }
    float ml = sl / (float)NE_, mi = si / (float)NE_;
    float vl = 0.f, vi = 0.f, sw = 0.f;
#pragma unroll
    for (int e = 0; e < NE_; e++) {
        vl += (ld[e] - ml) * (ld[e] - ml);
        vi += (imp[e] - mi) * (imp[e] - mi);
        sw += imp[e] * ld[e];
    }
    float cvl = sqrtf(vl / (float)(NE_ - 1)) / (ml + 1e-8f);
    float cvi = sqrtf(vi / (float)(NE_ - 1)) / (mi + 1e-8f);
    out[out_size - 1] = ((float)NE_ * sw + cvi + cvl) * LAMB_;
}

// ---------------- launch ----------------
extern "C" void kernel_launch(void* const* d_in, const int* in_sizes, int n_in,
                              void* d_out, int out_size) {
    const float* x   = (const float*)d_in[0];
    const float* gum = (const float*)d_in[1];
    const float* gw  = (const float*)d_in[2];
    const float* gb  = (const float*)d_in[3];
    const float* w1  = (const float*)d_in[4];
    const float* b1  = (const float*)d_in[5];
    const float* w2  = (const float*)d_in[6];
    const float* b2  = (const float*)d_in[7];
    float* out = (float*)d_out;

    float* xr  = nullptr; cudaGetSymbolAddress((void**)&xr,  g_xr);
    float* w1r = nullptr; cudaGetSymbolAddress((void**)&w1r, g_w1r);
    float* w2r = nullptr; cudaGetSymbolAddress((void**)&w2r, g_w2r);

    cudaFuncSetAttribute((const void*)gemm_cp<1>,
                         cudaFuncAttributeMaxDynamicSharedMemorySize, SMEM_BYTES);
    cudaFuncSetAttribute((const void*)gemm_cp<2>,
                         cudaFuncAttributeMaxDynamicSharedMemorySize, SMEM_BYTES);

    zero_kernel<<<1, 32>>>();
    round_kernel<<<1024, 256>>>(x,  xr,  (B_ * DIN_) / 4);
    round_kernel<<<2048, 256>>>(w1, w1r, (NE_ * DIN_ * DH_) / 4);
    round_kernel<<<2048, 256>>>(w2, w2r, (NE_ * DH_ * DOUT_) / 4);
    gate_kernel<<<B_ / 8, 256>>>(x, gum, gw, gb);

    gemm_cp<1><<<dim3(DH_ / BN, B_ / BM, NE_), 256, SMEM_BYTES>>>(xr, w1r, b1, nullptr);
    gemm_cp<2><<<dim3(DOUT_ / BN, B_ / BM), 256, SMEM_BYTES>>>(nullptr, w2r, b2, out);
    aux_kernel<<<1, 1>>>(out, out_size);
}

// round 6
// speedup vs baseline: 1.5549x; 1.0417x over previous
#include <cuda_runtime.h>
#include <cstdint>
#include <math.h>

#define B_    8192
#define DIN_  1024
#define DH_   2048
#define DOUT_ 1024
#define NE_   8
#define TAU_  0.8f
#define LAMB_ 0.05f

// block 128x256, 8 warps (2x4), warp tile 64x64, BK=32, 4 cp.async stages
#define BM 128
#define BN 256
#define BK 32
#define STAGES 4
#define A_STG (BM * BK)             // 4096 floats (XOR swizzle)
#define B_STG (BK * BN)             // 8192 floats (XOR swizzle)
#define STG_F (A_STG + B_STG)       // 12288 floats / stage
#define STG_BYTES (STG_F * 4)
#define SMEM_BYTES (STAGES * STG_BYTES + NE_ * BN * 4)

// -------- scratch (__device__ globals; no allocs allowed) --------
__device__ float g_probs[(size_t)B_ * NE_];
__device__ float g_sums[16];
__device__ float g_hprime[(size_t)B_ * NE_ * DH_];   // tf32-rounded h'
__device__ float g_xr[(size_t)B_ * DIN_];
__device__ float g_w1r[(size_t)NE_ * DIN_ * DH_];
__device__ float g_w2r[(size_t)NE_ * DH_ * DOUT_];

// ---------------- helpers ----------------
__device__ __forceinline__ uint32_t smem_u32(const void* p) {
    uint32_t a;
    asm("{ .reg .u64 t; cvta.to.shared.u64 t, %1; cvt.u32.u64 %0, t; }" : "=r"(a) : "l"(p));
    return a;
}
__device__ __forceinline__ float to_tf32(float v) {
    uint32_t u;
    asm("cvt.rna.tf32.f32 %0, %1;" : "=r"(u) : "f"(v));
    return __uint_as_float(u);
}
__device__ __forceinline__ void cpa16(uint32_t dst, const void* src) {
    asm volatile("cp.async.cg.shared.global [%0], [%1], 16;" :: "r"(dst), "l"(src));
}
#define CP_COMMIT() asm volatile("cp.async.commit_group;" ::: "memory")
#define CP_WAIT2()  asm volatile("cp.async.wait_group 2;" ::: "memory")

__device__ __forceinline__ void mma8(float* c, const uint32_t* a, const uint32_t* b) {
    asm volatile(
        "mma.sync.aligned.m16n8k8.row.col.f32.tf32.tf32.f32 "
        "{%0,%1,%2,%3},{%4,%5,%6,%7},{%8,%9},{%0,%1,%2,%3};"
        : "+f"(c[0]), "+f"(c[1]), "+f"(c[2]), "+f"(c[3])
        : "r"(a[0]), "r"(a[1]), "r"(a[2]), "r"(a[3]), "r"(b[0]), "r"(b[1]));
}

// ---------------- prep: tf32 rounding pass ----------------
__global__ __launch_bounds__(256) void round_kernel(const float* __restrict__ s0,
                                                    float* __restrict__ d0, int n0_,
                                                    const float* __restrict__ s1,
                                                    float* __restrict__ d1, int n1_) {
    int stride = gridDim.x * 256;
    for (int i = blockIdx.x * 256 + threadIdx.x; i < n0_; i += stride) {
        float4 v = ((const float4*)s0)[i];
        v.x = to_tf32(v.x); v.y = to_tf32(v.y);
        v.z = to_tf32(v.z); v.w = to_tf32(v.w);
        ((float4*)d0)[i] = v;
    }
    if (s1) {
        for (int i = blockIdx.x * 256 + threadIdx.x; i < n1_; i += stride) {
            float4 v = ((const float4*)s1)[i];
            v.x = to_tf32(v.x); v.y = to_tf32(v.y);
            v.z = to_tf32(v.z); v.w = to_tf32(v.w);
            ((float4*)d1)[i] = v;
        }
    }
}

// ---------------- main GEMM ----------------
// MODE 1: h' = tf32(probs * relu(xr @ w1r + b1)), grid.z = expert
// MODE 2: out = h' @ w2r_flat + sum_e probs*b2
template <int MODE>
__global__ __launch_bounds__(256, 1) void gemm_cp(const float* __restrict__ Aglob,
                                                  const float* __restrict__ Bglob,
                                                  const float* __restrict__ bias,
                                                  float* __restrict__ outp) {
    constexpr int KT  = (MODE == 1) ? (DIN_ / BK) : ((NE_ * DH_) / BK);
    constexpr int LDA = (MODE == 1) ? DIN_ : (NE_ * DH_);
    constexpr int LDB = (MODE == 1) ? DH_ : DOUT_;

    extern __shared__ float sm[];
    const int tid  = threadIdx.x;
    const int lane = tid & 31, warp = tid >> 5;
    const int g = lane >> 2, t = lane & 3;
    const int wm = warp >> 2, wn = warp & 3;     // 2x4 warps, warp tile 64x64

    const int e  = (MODE == 1) ? blockIdx.z : 0;
    const int m0 = blockIdx.y * BM;
    const int n0 = blockIdx.x * BN;
    const float* Ap = (MODE == 1) ? (Aglob + (size_t)m0 * LDA)
                                  : (g_hprime + (size_t)m0 * LDA);
    const float* Bp = (MODE == 1) ? (Bglob + (size_t)e * DIN_ * DH_ + n0)
                                  : (Bglob + n0);
    const uint32_t sbase = smem_u32(sm);

    if (MODE == 2) {
        for (int i = tid; i < NE_ * BN; i += 256) {
            int ee = i >> 8, c = i & 255;
            sm[STAGES * STG_F + i] = bias[(size_t)ee * DOUT_ + n0 + c];
        }
    }

    // per-thread precomputed copy descriptors
    const float* pA[4]; uint32_t soA[4];
    const float* pB[8]; uint32_t soB[8];
#pragma unroll
    for (int j = 0; j < 4; j++) {
        int id = tid + j * 256, m = id >> 3, kv = (id & 7) << 2;
        pA[j]  = Ap + (size_t)m * LDA + kv;
        soA[j] = (uint32_t)(m * 32 + (kv ^ ((m & 7) << 2))) * 4;
    }
#pragma unroll
    for (int j = 0; j < 8; j++) {
        int id = tid + j * 256, k = id >> 6, nv = (id & 63) << 2;
        pB[j]  = Bp + (size_t)k * LDB + nv;
        soB[j] = (uint32_t)(A_STG + k * 256 + (nv ^ ((k & 3) << 3))) * 4;
    }

    auto issue = [&](int kt) {
        uint32_t base = sbase + (uint32_t)(kt & 3) * STG_BYTES;
#pragma unroll
        for (int j = 0; j < 4; j++) { cpa16(base + soA[j], pA[j]); pA[j] += BK; }
#pragma unroll
        for (int j = 0; j < 8; j++) { cpa16(base + soB[j], pB[j]); pB[j] += (size_t)BK * LDB; }
    };

    float acc[4][8][4];
#pragma unroll
    for (int a = 0; a < 4; a++)
#pragma unroll
        for (int b = 0; b < 8; b++)
#pragma unroll
            for (int c = 0; c < 4; c++) acc[a][b][c] = 0.f;

    issue(0); CP_COMMIT();
    issue(1); CP_COMMIT();
    issue(2); CP_COMMIT();

    const int swa = g << 2;
    const int swb = t << 3;
    const int ma[4] = { wm * 64 + g, wm * 64 + 16 + g, wm * 64 + 32 + g, wm * 64 + 48 + g };
    const int nb[8] = { wn * 64 + g,      wn * 64 + 8 + g,  wn * 64 + 16 + g, wn * 64 + 24 + g,
                        wn * 64 + 32 + g, wn * 64 + 40 + g, wn * 64 + 48 + g, wn * 64 + 56 + g };

    uint32_t af[2][4][4], bf[2][8][2];

    auto load_frag = [&](const float* As, const float* Bs, int ks, int buf) {
        const int kk = ks * 8 + t;
        const int ka = kk ^ swa, ka4 = (kk + 4) ^ swa;
#pragma unroll
        for (int mt = 0; mt < 4; mt++) {
            int m = ma[mt];
            af[buf][mt][0] = __float_as_uint(As[m * 32 + ka]);
            af[buf][mt][1] = __float_as_uint(As[(m + 8) * 32 + ka]);
            af[buf][mt][2] = __float_as_uint(As[m * 32 + ka4]);
            af[buf][mt][3] = __float_as_uint(As[(m + 8) * 32 + ka4]);
        }
#pragma unroll
        for (int nt = 0; nt < 8; nt++) {
            int n = nb[nt] ^ swb;
            bf[buf][nt][0] = __float_as_uint(Bs[kk * 256 + n]);
            bf[buf][nt][1] = __float_as_uint(Bs[(kk + 4) * 256 + n]);
        }
    };

    for (int kt = 0; kt < KT; kt++) {
        CP_WAIT2();
        __syncthreads();
        const float* As = sm + (size_t)(kt & 3) * STG_F;
        const float* Bs = As + A_STG;

        load_frag(As, Bs, 0, 0);          // ks0 frags first...
        if (kt + 3 < KT) issue(kt + 3);   // ...overlap LDS latency with LDGSTS issue
        CP_COMMIT();

#pragma unroll
        for (int ks = 0; ks < 4; ks++) {
            const int cur = ks & 1;
            if (ks < 3) load_frag(As, Bs, ks + 1, cur ^ 1);
#pragma unroll
            for (int mt = 0; mt < 4; mt++)
#pragma unroll
                for (int nt = 0; nt < 8; nt++)
                    mma8(acc[mt][nt], af[cur][mt], bf[cur][nt]);
        }
    }
    __syncthreads();

    // ---------------- epilogue ----------------
#pragma unroll
    for (int mt = 0; mt < 4; mt++) {
        const int r0 = m0 + wm * 64 + mt * 16 + g;   // rows r0, r0+8
        float p0 = 0.f, p1 = 0.f;
        float pr0[NE_], pr1[NE_];
        if (MODE == 1) {
            p0 = g_probs[(size_t)r0 * NE_ + e];
            p1 = g_probs[(size_t)(r0 + 8) * NE_ + e];
        } else {
#pragma unroll
            for (int ee = 0; ee < NE_; ee++) {
                pr0[ee] = g_probs[(size_t)r0 * NE_ + ee];
                pr1[ee] = g_probs[(size_t)(r0 + 8) * NE_ + ee];
            }
        }
#pragma unroll
        for (int nt = 0; nt < 8; nt++) {
            const int c = wn * 64 + nt * 8 + 2 * t;
            if (MODE == 1) {
                float2 bv = *(const float2*)(bias + (size_t)e * DH_ + n0 + c);
                float2 v0, v1;
                v0.x = to_tf32(p0 * fmaxf(acc[mt][nt][0] + bv.x, 0.f));
                v0.y = to_tf32(p0 * fmaxf(acc[mt][nt][1] + bv.y, 0.f));
                v1.x = to_tf32(p1 * fmaxf(acc[mt][nt][2] + bv.x, 0.f));
                v1.y = to_tf32(p1 * fmaxf(acc[mt][nt][3] + bv.y, 0.f));
                size_t base = (size_t)e * DH_ + n0 + c;
                *(float2*)(g_hprime + (size_t)r0 * (NE_ * DH_) + base) = v0;
                *(float2*)(g_hprime + (size_t)(r0 + 8) * (NE_ * DH_) + base) = v1;
            } else {
                const float* b2s = sm + STAGES * STG_F;
                float bx0 = 0.f, by0 = 0.f, bx1 = 0.f, by1 = 0.f;
#pragma unroll
                for (int ee = 0; ee < NE_; ee++) {
                    float bx = b2s[ee * BN + c], by = b2s[ee * BN + c + 1];
                    bx0 += pr0[ee] * bx; by0 += pr0[ee] * by;
                    bx1 += pr1[ee] * bx; by1 += pr1[ee] * by;
                }
                float2 v0 = make_float2(acc[mt][nt][0] + bx0, acc[mt][nt][1] + by0);
                float2 v1 = make_float2(acc[mt][nt][2] + bx1, acc[mt][nt][3] + by1);
                *(float2*)(outp + (size_t)r0 * DOUT_ + n0 + c) = v0;
                *(float2*)(outp + (size_t)(r0 + 8) * DOUT_ + n0 + c) = v1;
            }
        }
    }
}

// ---------------- gating / aux ----------------
__global__ void zero_kernel() {
    if (threadIdx.x < 16) g_sums[threadIdx.x] = 0.f;
}

__global__ __launch_bounds__(256) void gate_kernel(const float* __restrict__ x,
                                                   const float* __restrict__ gum,
                                                   const float* __restrict__ gw,
                                                   const float* __restrict__ gb) {
    __shared__ float psum[16];
    int tid = threadIdx.x;
    if (tid < 16) psum[tid] = 0.f;
    __syncthreads();
    int warp = tid >> 5, lane = tid & 31;
    int row = blockIdx.x * 8 + warp;

    float acc[NE_];
#pragma unroll
    for (int e = 0; e < NE_; e++) acc[e] = 0.f;
    const float* xr = x + (size_t)row * DIN_;
    for (int k = lane; k < DIN_; k += 32) {
        float xv = xr[k];
        float4 w0 = *(const float4*)(gw + (size_t)k * NE_);
        float4 w1v = *(const float4*)(gw + (size_t)k * NE_ + 4);
        acc[0] += xv * w0.x;  acc[1] += xv * w0.y;
        acc[2] += xv * w0.z;  acc[3] += xv * w0.w;
        acc[4] += xv * w1v.x; acc[5] += xv * w1v.y;
        acc[6] += xv * w1v.z; acc[7] += xv * w1v.w;
    }
#pragma unroll
    for (int e = 0; e < NE_; e++) {
#pragma unroll
        for (int off = 16; off > 0; off >>= 1)
            acc[e] += __shfl_xor_sync(0xffffffffu, acc[e], off);
    }
    if (lane == 0) {
        float s1[NE_], s2[NE_];
        float m1 = -1e30f, m2 = -1e30f;
#pragma unroll
        for (int e = 0; e < NE_; e++) {
            float lg = acc[e] + gb[e];
            s1[e] = (lg + gum[(size_t)row * NE_ + e]) * (1.0f / TAU_);
            s2[e] = lg * (1.0f / TAU_);
            m1 = fmaxf(m1, s1[e]); m2 = fmaxf(m2, s2[e]);
        }
        float d1 = 0.f, d2 = 0.f;
#pragma unroll
        for (int e = 0; e < NE_; e++) {
            s1[e] = expf(s1[e] - m1); s2[e] = expf(s2[e] - m2);
            d1 += s1[e]; d2 += s2[e];
        }
#pragma unroll
        for (int e = 0; e < NE_; e++) {
            float p = s1[e] / d1, r = s2[e] / d2;
            g_probs[(size_t)row * NE_ + e] = p;
            atomicAdd(&psum[e], p);
            atomicAdd(&psum[8 + e], r);
        }
    }
    __syncthreads();
    if (tid < 16) atomicAdd(&g_sums[tid], psum[tid]);
}

__global__ void aux_kernel(float* __restrict__ out, int out_size) {
    if (threadIdx.x != 0 || blockIdx.x != 0) return;
    float ld[NE_], imp[NE_];
    float sl = 0.f, si = 0.f;
#pragma unroll
    for (int e = 0; e < NE_; e++) {
        ld[e]  = g_sums[e] / (float)B_;
        imp[e] = g_sums[8 + e] / (float)B_;
        sl += ld[e]; si += imp[e];
    }
    float ml = sl / (float)NE_, mi = si / (float)NE_;
    float vl = 0.f, vi = 0.f, sw = 0.f;
#pragma unroll
    for (int e = 0; e < NE_; e++) {
        vl += (ld[e] - ml) * (ld[e] - ml);
        vi += (imp[e] - mi) * (imp[e] - mi);
        sw += imp[e] * ld[e];
    }
    float cvl = sqrtf(vl / (float)(NE_ - 1)) / (ml + 1e-8f);
    float cvi = sqrtf(vi / (float)(NE_ - 1)) / (mi + 1e-8f);
    out[out_size - 1] = ((float)NE_ * sw + cvi + cvl) * LAMB_;
}

// ---------------- launch ----------------
extern "C" void kernel_launch(void* const* d_in, const int* in_sizes, int n_in,
                              void* d_out, int out_size) {
    const float* x   = (const float*)d_in[0];
    const float* gum = (const float*)d_in[1];
    const float* gw  = (const float*)d_in[2];
    const float* gb  = (const float*)d_in[3];
    const float* w1  = (const float*)d_in[4];
    const float* b1  = (const float*)d_in[5];
    const float* w2  = (const float*)d_in[6];
    const float* b2  = (const float*)d_in[7];
    float* out = (float*)d_out;

    float* xr  = nullptr; cudaGetSymbolAddress((void**)&xr,  g_xr);
    float* w1r = nullptr; cudaGetSymbolAddress((void**)&w1r, g_w1r);
    float* w2r = nullptr; cudaGetSymbolAddress((void**)&w2r, g_w2r);

    cudaFuncSetAttribute((const void*)gemm_cp<1>,
                         cudaFuncAttributeMaxDynamicSharedMemorySize, SMEM_BYTES);
    cudaFuncSetAttribute((const void*)gemm_cp<2>,
                         cudaFuncAttributeMaxDynamicSharedMemorySize, SMEM_BYTES);

    // launch order chosen so ncu (-s 5 -c 1) lands on gemm2
    zero_kernel<<<1, 32>>>();
    round_kernel<<<1024, 256>>>(x, xr, (B_ * DIN_) / 4, nullptr, nullptr, 0);
    round_kernel<<<2048, 256>>>(w1, w1r, (NE_ * DIN_ * DH_) / 4,
                                w2, w2r, (NE_ * DH_ * DOUT_) / 4);
    gate_kernel<<<B_ / 8, 256>>>(x, gum, gw, gb);
    gemm_cp<1><<<dim3(DH_ / BN, B_ / BM, NE_), 256, SMEM_BYTES>>>(xr, w1r, b1, nullptr);
    gemm_cp<2><<<dim3(DOUT_ / BN, B_ / BM), 256, SMEM_BYTES>>>(nullptr, w2r, b2, out);
    aux_kernel<<<1, 1>>>(out, out_size);
}

// round 7
// speedup vs baseline: 2.8305x; 1.8204x over previous
#include <cuda_runtime.h>
#include <cuda_fp16.h>
#include <cstdint>
#include <math.h>

#define B_    8192
#define DIN_  1024
#define DH_   2048
#define DOUT_ 1024
#define NE_   8
#define TAU_  0.8f
#define LAMB_ 0.05f

// block 128x256, 8 warps (2x4), warp tile 64x64, BK=32 halves, 6 cp.async stages
#define BM 128
#define BN 256
#define BK 32
#define STAGES 6
#define A_BYTES (BM * BK * 2)        // 8192
#define B_BYTES (BK * BN * 2)        // 16384
#define STG_BYTES (A_BYTES + B_BYTES) // 24576
#define SMEM_BYTES (STAGES * STG_BYTES + NE_ * BN * 4)

// -------- scratch (__device__ globals; 16B-aligned via uint4) --------
__device__ float g_probs[(size_t)B_ * NE_];
__device__ float g_sums[16];
__device__ uint4 g_xh4[(size_t)B_ * DIN_ / 8];          // fp16 x
__device__ uint4 g_w1h4[(size_t)NE_ * DIN_ * DH_ / 8];  // fp16 w1
__device__ uint4 g_w2h4[(size_t)NE_ * DH_ * DOUT_ / 8]; // fp16 w2
__device__ uint4 g_hp4[(size_t)B_ * NE_ * DH_ / 8];     // fp16 h' [B][E*Dh]

// ---------------- helpers ----------------
__device__ __forceinline__ uint32_t smem_u32(const void* p) {
    uint32_t a;
    asm("{ .reg .u64 t; cvta.to.shared.u64 t, %1; cvt.u32.u64 %0, t; }" : "=r"(a) : "l"(p));
    return a;
}
__device__ __forceinline__ void cpa16(uint32_t dst, const void* src) {
    asm volatile("cp.async.cg.shared.global [%0], [%1], 16;" :: "r"(dst), "l"(src));
}
#define CP_COMMIT() asm volatile("cp.async.commit_group;" ::: "memory")
#define CP_WAIT4()  asm volatile("cp.async.wait_group 4;" ::: "memory")

__device__ __forceinline__ void ldsm4(uint32_t* r, uint32_t addr) {
    asm volatile("ldmatrix.sync.aligned.m8n8.x4.shared.b16 {%0,%1,%2,%3}, [%4];"
        : "=r"(r[0]), "=r"(r[1]), "=r"(r[2]), "=r"(r[3]) : "r"(addr));
}
__device__ __forceinline__ void ldsm4t(uint32_t* r, uint32_t addr) {
    asm volatile("ldmatrix.sync.aligned.m8n8.x4.trans.shared.b16 {%0,%1,%2,%3}, [%4];"
        : "=r"(r[0]), "=r"(r[1]), "=r"(r[2]), "=r"(r[3]) : "r"(addr));
}
__device__ __forceinline__ void mma16(float* c, const uint32_t* a, const uint32_t* b) {
    asm volatile(
        "mma.sync.aligned.m16n8k16.row.col.f32.f16.f16.f32 "
        "{%0,%1,%2,%3},{%4,%5,%6,%7},{%8,%9},{%0,%1,%2,%3};"
        : "+f"(c[0]), "+f"(c[1]), "+f"(c[2]), "+f"(c[3])
        : "r"(a[0]), "r"(a[1]), "r"(a[2]), "r"(a[3]), "r"(b[0]), "r"(b[1]));
}

// ---------------- prep: fp32 -> fp16 ----------------
__global__ __launch_bounds__(256) void half_kernel(const float* __restrict__ s0,
                                                   __half* __restrict__ d0, int n0_,
                                                   const float* __restrict__ s1,
                                                   __half* __restrict__ d1, int n1_) {
    int stride = gridDim.x * 256;
    for (int i = blockIdx.x * 256 + threadIdx.x; i < n0_; i += stride) {
        float4 v = ((const float4*)s0)[i];
        __half2 h0 = __floats2half2_rn(v.x, v.y);
        __half2 h1 = __floats2half2_rn(v.z, v.w);
        ((__half2*)d0)[2 * i]     = h0;
        ((__half2*)d0)[2 * i + 1] = h1;
    }
    if (s1) {
        for (int i = blockIdx.x * 256 + threadIdx.x; i < n1_; i += stride) {
            float4 v = ((const float4*)s1)[i];
            __half2 h0 = __floats2half2_rn(v.x, v.y);
            __half2 h1 = __floats2half2_rn(v.z, v.w);
            ((__half2*)d1)[2 * i]     = h0;
            ((__half2*)d1)[2 * i + 1] = h1;
        }
    }
}

// ---------------- main GEMM (fp16 inputs, fp32 accum) ----------------
// MODE 1: h' = fp16(probs * relu(xh @ w1h + b1)), grid.z = expert
// MODE 2: out = hp @ w2h_flat + sum_e probs*b2
template <int MODE>
__global__ __launch_bounds__(256, 1) void gemm_h(const __half* __restrict__ Aglob,
                                                 const __half* __restrict__ Bglob,
                                                 const float* __restrict__ bias,
                                                 float* __restrict__ outp) {
    constexpr int KT  = (MODE == 1) ? (DIN_ / BK) : ((NE_ * DH_) / BK);
    constexpr int LDA = (MODE == 1) ? DIN_ : (NE_ * DH_);     // halves
    constexpr int LDB = (MODE == 1) ? DH_ : DOUT_;            // halves

    extern __shared__ float sm[];
    const int tid  = threadIdx.x;
    const int lane = tid & 31, warp = tid >> 5;
    const int g = lane >> 2, t = lane & 3;
    const int wm = warp >> 2, wn = warp & 3;     // 2x4 warps, warp tile 64x64

    const int e  = (MODE == 1) ? blockIdx.z : 0;
    const int m0 = blockIdx.y * BM;
    const int n0 = blockIdx.x * BN;
    const __half* hp = (const __half*)g_hp4;
    const __half* Ap = (MODE == 1) ? (Aglob + (size_t)m0 * LDA)
                                   : (hp + (size_t)m0 * LDA);
    const __half* Bp = (MODE == 1) ? (Bglob + (size_t)e * DIN_ * DH_ + n0)
                                   : (Bglob + n0);
    const uint32_t sbase = smem_u32(sm);
    float* b2s = sm + (STAGES * STG_BYTES) / 4;

    if (MODE == 2) {
        for (int i = tid; i < NE_ * BN; i += 256) {
            int ee = i >> 8, c = i & 255;
            b2s[i] = bias[(size_t)ee * DOUT_ + n0 + c];
        }
    }

    // per-thread copy descriptors
    // A tile: 128 rows x 32 halves (4 chunks of 16B). phys chunk(m,c) = (m>>1)*8 + ((((m&1)<<2)|c) ^ ((m>>1)&7))
    // B tile: 32 rows x 256 halves (32 chunks).      phys chunk(k,cn) = k*32 + (cn ^ (k&7))
    const __half* pA[2]; uint32_t soA[2];
    const __half* pB[4]; uint32_t soB[4];
#pragma unroll
    for (int j = 0; j < 2; j++) {
        int id = tid + j * 256, m = id >> 2, c = id & 3;
        pA[j]  = Ap + (size_t)m * LDA + c * 8;
        soA[j] = (uint32_t)(((m >> 1) << 3) + ((((m & 1) << 2) | c) ^ ((m >> 1) & 7))) * 16;
    }
#pragma unroll
    for (int j = 0; j < 4; j++) {
        int id = tid + j * 256, k = id >> 5, cn = id & 31;
        pB[j]  = Bp + (size_t)k * LDB + cn * 8;
        soB[j] = (uint32_t)(A_BYTES) + (uint32_t)(k * 32 + (cn ^ (k & 7))) * 16;
    }

    auto issue = [&](uint32_t stg) {
#pragma unroll
        for (int j = 0; j < 2; j++) { cpa16(stg + soA[j], pA[j]); pA[j] += BK; }
#pragma unroll
        for (int j = 0; j < 4; j++) { cpa16(stg + soB[j], pB[j]); pB[j] += (size_t)BK * LDB; }
    };

    float acc[4][8][4];
#pragma unroll
    for (int a = 0; a < 4; a++)
#pragma unroll
        for (int b = 0; b < 8; b++)
#pragma unroll
            for (int c = 0; c < 4; c++) acc[a][b][c] = 0.f;

    // prologue: 5 stages in flight
#pragma unroll
    for (int p = 0; p < 5; p++) { issue(sbase + p * STG_BYTES); CP_COMMIT(); }

    // ldmatrix per-lane precomputes
    const int mat = lane >> 3, mr = lane & 7;
    const int matc = mat >> 1, matm = (mat & 1) << 3;
    // A: per mt, m = wm*64 + mt*16 + matm + mr
    uint32_t a_b8[4], a_e[4], a_hm[4];
#pragma unroll
    for (int mt = 0; mt < 4; mt++) {
        int m = wm * 64 + mt * 16 + matm + mr;
        a_b8[mt] = (uint32_t)((m >> 1) << 3);
        a_e[mt]  = (uint32_t)((m >> 1) & 7);
        a_hm[mt] = (uint32_t)((m & 1) << 2);
    }
    // B: per ntp (pair of nt), k = ks*16 + matm + mr; cn = wn*8 + ntp*2 + matc
    uint32_t b_cb[4];
#pragma unroll
    for (int ntp = 0; ntp < 4; ntp++) {
        int kb = matm + mr;
        int cn = wn * 8 + ntp * 2 + matc;
        b_cb[ntp] = (uint32_t)(kb * 32 + (cn ^ mr)) * 16;
    }

    int istage = 5, cs = 0;
    for (int kt = 0; kt < KT; kt++) {
        CP_WAIT4();
        __syncthreads();
        if (kt + 5 < KT) issue(sbase + (uint32_t)istage * STG_BYTES);
        CP_COMMIT();
        if (++istage == STAGES) istage = 0;
        const uint32_t stg = sbase + (uint32_t)cs * STG_BYTES;
        if (++cs == STAGES) cs = 0;

        uint32_t aF[2][4][4], bF[2][8][2];
#pragma unroll
        for (int ks = 0; ks < 2; ks++) {
            const uint32_t cA = (uint32_t)(ks * 2 + matc);
#pragma unroll
            for (int mt = 0; mt < 4; mt++) {
                uint32_t ch = a_b8[mt] + ((a_hm[mt] | cA) ^ a_e[mt]);
                ldsm4(aF[ks][mt], stg + ch * 16);
            }
            const uint32_t bbase = stg + (uint32_t)A_BYTES + (uint32_t)ks * 8192u;
#pragma unroll
            for (int ntp = 0; ntp < 4; ntp++) {
                uint32_t rr[4];
                ldsm4t(rr, bbase + b_cb[ntp]);
                bF[ks][2 * ntp][0] = rr[0]; bF[ks][2 * ntp][1] = rr[1];
                bF[ks][2 * ntp + 1][0] = rr[2]; bF[ks][2 * ntp + 1][1] = rr[3];
            }
        }
#pragma unroll
        for (int ks = 0; ks < 2; ks++)
#pragma unroll
            for (int mt = 0; mt < 4; mt++)
#pragma unroll
                for (int nt = 0; nt < 8; nt++)
                    mma16(acc[mt][nt], aF[ks][mt], bF[ks][nt]);
    }
    __syncthreads();

    // ---------------- epilogue ----------------
    __half* hpw = (__half*)g_hp4;
#pragma unroll
    for (int mt = 0; mt < 4; mt++) {
        const int r0 = m0 + wm * 64 + mt * 16 + g;   // rows r0, r0+8
        float p0 = 0.f, p1 = 0.f;
        float pr0[NE_], pr1[NE_];
        if (MODE == 1) {
            p0 = g_probs[(size_t)r0 * NE_ + e];
            p1 = g_probs[(size_t)(r0 + 8) * NE_ + e];
        } else {
#pragma unroll
            for (int ee = 0; ee < NE_; ee++) {
                pr0[ee] = g_probs[(size_t)r0 * NE_ + ee];
                pr1[ee] = g_probs[(size_t)(r0 + 8) * NE_ + ee];
            }
        }
#pragma unroll
        for (int nt = 0; nt < 8; nt++) {
            const int c = wn * 64 + nt * 8 + 2 * t;
            if (MODE == 1) {
                float2 bv = *(const float2*)(bias + (size_t)e * DH_ + n0 + c);
                __half2 v0 = __floats2half2_rn(p0 * fmaxf(acc[mt][nt][0] + bv.x, 0.f),
                                               p0 * fmaxf(acc[mt][nt][1] + bv.y, 0.f));
                __half2 v1 = __floats2half2_rn(p1 * fmaxf(acc[mt][nt][2] + bv.x, 0.f),
                                               p1 * fmaxf(acc[mt][nt][3] + bv.y, 0.f));
                size_t base = (size_t)e * DH_ + n0 + c;
                *(__half2*)(hpw + (size_t)r0 * (NE_ * DH_) + base) = v0;
                *(__half2*)(hpw + (size_t)(r0 + 8) * (NE_ * DH_) + base) = v1;
            } else {
                float bx0 = 0.f, by0 = 0.f, bx1 = 0.f, by1 = 0.f;
#pragma unroll
                for (int ee = 0; ee < NE_; ee++) {
                    float bx = b2s[ee * BN + c], by = b2s[ee * BN + c + 1];
                    bx0 += pr0[ee] * bx; by0 += pr0[ee] * by;
                    bx1 += pr1[ee] * bx; by1 += pr1[ee] * by;
                }
                float2 v0 = make_float2(acc[mt][nt][0] + bx0, acc[mt][nt][1] + by0);
                float2 v1 = make_float2(acc[mt][nt][2] + bx1, acc[mt][nt][3] + by1);
                *(float2*)(outp + (size_t)r0 * DOUT_ + n0 + c) = v0;
                *(float2*)(outp + (size_t)(r0 + 8) * DOUT_ + n0 + c) = v1;
            }
        }
    }
}

// ---------------- gating / aux ----------------
__global__ void zero_kernel() {
    if (threadIdx.x < 16) g_sums[threadIdx.x] = 0.f;
}

__global__ __launch_bounds__(256) void gate_kernel(const float* __restrict__ x,
                                                   const float* __restrict__ gum,
                                                   const float* __restrict__ gw,
                                                   const float* __restrict__ gb) {
    __shared__ float psum[16];
    int tid = threadIdx.x;
    if (tid < 16) psum[tid] = 0.f;
    __syncthreads();
    int warp = tid >> 5, lane = tid & 31;
    int row = blockIdx.x * 8 + warp;

    float acc[NE_];
#pragma unroll
    for (int e = 0; e < NE_; e++) acc[e] = 0.f;
    const float* xr = x + (size_t)row * DIN_;
    for (int k = lane; k < DIN_; k += 32) {
        float xv = xr[k];
        float4 w0 = *(const float4*)(gw + (size_t)k * NE_);
        float4 w1v = *(const float4*)(gw + (size_t)k * NE_ + 4);
        acc[0] += xv * w0.x;  acc[1] += xv * w0.y;
        acc[2] += xv * w0.z;  acc[3] += xv * w0.w;
        acc[4] += xv * w1v.x; acc[5] += xv * w1v.y;
        acc[6] += xv * w1v.z; acc[7] += xv * w1v.w;
    }
#pragma unroll
    for (int e = 0; e < NE_; e++) {
#pragma unroll
        for (int off = 16; off > 0; off >>= 1)
            acc[e] += __shfl_xor_sync(0xffffffffu, acc[e], off);
    }
    if (lane == 0) {
        float s1[NE_], s2[NE_];
        float m1 = -1e30f, m2 = -1e30f;
#pragma unroll
        for (int e = 0; e < NE_; e++) {
            float lg = acc[e] + gb[e];
            s1[e] = (lg + gum[(size_t)row * NE_ + e]) * (1.0f / TAU_);
            s2[e] = lg * (1.0f / TAU_);
            m1 = fmaxf(m1, s1[e]); m2 = fmaxf(m2, s2[e]);
        }
        float d1 = 0.f, d2 = 0.f;
#pragma unroll
        for (int e = 0; e < NE_; e++) {
            s1[e] = expf(s1[e] - m1); s2[e] = expf(s2[e] - m2);
            d1 += s1[e]; d2 += s2[e];
        }
#pragma unroll
        for (int e = 0; e < NE_; e++) {
            float p = s1[e] / d1, r = s2[e] / d2;
            g_probs[(size_t)row * NE_ + e] = p;
            atomicAdd(&psum[e], p);
            atomicAdd(&psum[8 + e], r);
        }
    }
    __syncthreads();
    if (tid < 16) atomicAdd(&g_sums[tid], psum[tid]);
}

__global__ void aux_kernel(float* __restrict__ out, int out_size) {
    if (threadIdx.x != 0 || blockIdx.x != 0) return;
    float ld[NE_], imp[NE_];
    float sl = 0.f, si = 0.f;
#pragma unroll
    for (int e = 0; e < NE_; e++) {
        ld[e]  = g_sums[e] / (float)B_;
        imp[e] = g_sums[8 + e] / (float)B_;
        sl += ld[e]; si += imp[e];
    }
    float ml = sl / (float)NE_, mi = si / (float)NE_;
    float vl = 0.f, vi = 0.f, sw = 0.f;
#pragma unroll
    for (int e = 0; e < NE_; e++) {
        vl += (ld[e] - ml) * (ld[e] - ml);
        vi += (imp[e] - mi) * (imp[e] - mi);
        sw += imp[e] * ld[e];
    }
    float cvl = sqrtf(vl / (float)(NE_ - 1)) / (ml + 1e-8f);
    float cvi = sqrtf(vi / (float)(NE_ - 1)) / (mi + 1e-8f);
    out[out_size - 1] = ((float)NE_ * sw + cvi + cvl) * LAMB_;
}

// ---------------- launch ----------------
extern "C" void kernel_launch(void* const* d_in, const int* in_sizes, int n_in,
                              void* d_out, int out_size) {
    const float* x   = (const float*)d_in[0];
    const float* gum = (const float*)d_in[1];
    const float* gw  = (const float*)d_in[2];
    const float* gb  = (const float*)d_in[3];
    const float* w1  = (const float*)d_in[4];
    const float* b1  = (const float*)d_in[5];
    const float* w2  = (const float*)d_in[6];
    const float* b2  = (const float*)d_in[7];
    float* out = (float*)d_out;

    __half *xh = nullptr, *w1h = nullptr, *w2h = nullptr;
    cudaGetSymbolAddress((void**)&xh,  g_xh4);
    cudaGetSymbolAddress((void**)&w1h, g_w1h4);
    cudaGetSymbolAddress((void**)&w2h, g_w2h4);

    cudaFuncSetAttribute((const void*)gemm_h<1>,
                         cudaFuncAttributeMaxDynamicSharedMemorySize, SMEM_BYTES);
    cudaFuncSetAttribute((const void*)gemm_h<2>,
                         cudaFuncAttributeMaxDynamicSharedMemorySize, SMEM_BYTES);

    zero_kernel<<<1, 32>>>();
    half_kernel<<<1024, 256>>>(x, xh, (B_ * DIN_) / 4, nullptr, nullptr, 0);
    half_kernel<<<2048, 256>>>(w1, w1h, (NE_ * DIN_ * DH_) / 4,
                               w2, w2h, (NE_ * DH_ * DOUT_) / 4);
    gate_kernel<<<B_ / 8, 256>>>(x, gum, gw, gb);
    gemm_h<1><<<dim3(DH_ / BN, B_ / BM, NE_), 256, SMEM_BYTES>>>(xh, w1h, b1, nullptr);
    gemm_h<2><<<dim3(DOUT_ / BN, B_ / BM), 256, SMEM_BYTES>>>(nullptr, w2h, b2, out);
    aux_kernel<<<1, 1>>>(out, out_size);
}

// round 8
// speedup vs baseline: 3.1031x; 1.0963x over previous
#include <cuda_runtime.h>
#include <cuda_fp16.h>
#include <cstdint>
#include <math.h>

#define B_    8192
#define DIN_  1024
#define DH_   2048
#define DOUT_ 1024
#define NE_   8
#define TAU_  0.8f
#define LAMB_ 0.05f

// block 128x256, 16 warps (4x4), warp tile 32x64, BK=32 halves, 6 cp.async stages
#define BM 128
#define BN 256
#define BK 32
#define NT 512
#define STAGES 6
#define A_BYTES (BM * BK * 2)         // 8192
#define B_BYTES (BK * BN * 2)         // 16384
#define STG_BYTES (A_BYTES + B_BYTES) // 24576
#define SMEM_BYTES (STAGES * STG_BYTES)
#define KSPLIT 4

// -------- scratch (__device__ globals; 16B-aligned via uint4) --------
__device__ float g_probs[(size_t)B_ * NE_];
__device__ float g_sums[16];
__device__ uint4 g_xh4[(size_t)B_ * DIN_ / 8];
__device__ uint4 g_w1h4[(size_t)NE_ * DIN_ * DH_ / 8];
__device__ uint4 g_w2h4[(size_t)NE_ * DH_ * DOUT_ / 8];
__device__ uint4 g_hp4[(size_t)B_ * NE_ * DH_ / 8];       // fp16 h' [B][E*Dh]
__device__ float g_part[(size_t)KSPLIT * B_ * DOUT_];     // split-K partials

// ---------------- helpers ----------------
__device__ __forceinline__ uint32_t smem_u32(const void* p) {
    uint32_t a;
    asm("{ .reg .u64 t; cvta.to.shared.u64 t, %1; cvt.u32.u64 %0, t; }" : "=r"(a) : "l"(p));
    return a;
}
__device__ __forceinline__ void cpa16(uint32_t dst, const void* src) {
    asm volatile("cp.async.cg.shared.global [%0], [%1], 16;" :: "r"(dst), "l"(src));
}
#define CP_COMMIT() asm volatile("cp.async.commit_group;" ::: "memory")
#define CP_WAIT4()  asm volatile("cp.async.wait_group 4;" ::: "memory")

__device__ __forceinline__ void ldsm4(uint32_t* r, uint32_t addr) {
    asm volatile("ldmatrix.sync.aligned.m8n8.x4.shared.b16 {%0,%1,%2,%3}, [%4];"
        : "=r"(r[0]), "=r"(r[1]), "=r"(r[2]), "=r"(r[3]) : "r"(addr));
}
__device__ __forceinline__ void ldsm4t(uint32_t* r, uint32_t addr) {
    asm volatile("ldmatrix.sync.aligned.m8n8.x4.trans.shared.b16 {%0,%1,%2,%3}, [%4];"
        : "=r"(r[0]), "=r"(r[1]), "=r"(r[2]), "=r"(r[3]) : "r"(addr));
}
__device__ __forceinline__ void mma16(float* c, const uint32_t* a, const uint32_t* b) {
    asm volatile(
        "mma.sync.aligned.m16n8k16.row.col.f32.f16.f16.f32 "
        "{%0,%1,%2,%3},{%4,%5,%6,%7},{%8,%9},{%0,%1,%2,%3};"
        : "+f"(c[0]), "+f"(c[1]), "+f"(c[2]), "+f"(c[3])
        : "r"(a[0]), "r"(a[1]), "r"(a[2]), "r"(a[3]), "r"(b[0]), "r"(b[1]));
}

// ---------------- prep: fp32 -> fp16 (all three tensors) ----------------
__global__ __launch_bounds__(256) void half_kernel(const float* __restrict__ s0,
                                                   __half* __restrict__ d0, int n0_,
                                                   const float* __restrict__ s1,
                                                   __half* __restrict__ d1, int n1_,
                                                   const float* __restrict__ s2,
                                                   __half* __restrict__ d2, int n2_) {
    int stride = gridDim.x * 256;
    int t0 = blockIdx.x * 256 + threadIdx.x;
    for (int i = t0; i < n0_; i += stride) {
        float4 v = ((const float4*)s0)[i];
        ((__half2*)d0)[2 * i]     = __floats2half2_rn(v.x, v.y);
        ((__half2*)d0)[2 * i + 1] = __floats2half2_rn(v.z, v.w);
    }
    for (int i = t0; i < n1_; i += stride) {
        float4 v = ((const float4*)s1)[i];
        ((__half2*)d1)[2 * i]     = __floats2half2_rn(v.x, v.y);
        ((__half2*)d1)[2 * i + 1] = __floats2half2_rn(v.z, v.w);
    }
    for (int i = t0; i < n2_; i += stride) {
        float4 v = ((const float4*)s2)[i];
        ((__half2*)d2)[2 * i]     = __floats2half2_rn(v.x, v.y);
        ((__half2*)d2)[2 * i + 1] = __floats2half2_rn(v.z, v.w);
    }
}

// ---------------- main GEMM (fp16 in, fp32 accum), 512 threads ----------------
// MODE 1: h' = fp16(probs * relu(xh @ w1h + b1)), grid.z = expert, KT=32
// MODE 2: part[kq] = hp[:, kq*4096:(kq+1)*4096] @ w2h[kq slice], grid.z = kq, KT=128
template <int MODE>
__global__ __launch_bounds__(NT, 1) void gemm_h(const __half* __restrict__ Aglob,
                                                const __half* __restrict__ Bglob,
                                                const float* __restrict__ bias) {
    constexpr int KT  = (MODE == 1) ? (DIN_ / BK) : (NE_ * DH_ / BK / KSPLIT);
    constexpr int LDA = (MODE == 1) ? DIN_ : (NE_ * DH_);
    constexpr int LDB = (MODE == 1) ? DH_ : DOUT_;

    extern __shared__ float sm[];
    const int tid  = threadIdx.x;
    const int lane = tid & 31, warp = tid >> 5;
    const int g = lane >> 2, t = lane & 3;
    const int wm = warp >> 2, wn = warp & 3;     // 4x4 warps, warp tile 32x64

    const int e  = blockIdx.z;                   // expert (MODE1) or kq (MODE2)
    const int m0 = blockIdx.y * BM;
    const int n0 = blockIdx.x * BN;
    const __half* hp = (const __half*)g_hp4;
    const __half* Ap = (MODE == 1) ? (Aglob + (size_t)m0 * LDA)
                                   : (hp + (size_t)m0 * LDA + (size_t)e * (NE_ * DH_ / KSPLIT));
    const __half* Bp = (MODE == 1)
        ? (Bglob + (size_t)e * DIN_ * DH_ + n0)
        : (Bglob + (size_t)e * (NE_ * DH_ / KSPLIT) * LDB + n0);
    const uint32_t sbase = smem_u32(sm);

    // copy descriptors (512 threads): A 512 chunks (1/thr), B 1024 chunks (2/thr)
    const __half* pA; uint32_t soA;
    const __half* pB[2]; uint32_t soB[2];
    {
        int m = tid >> 2, c = tid & 3;
        pA  = Ap + (size_t)m * LDA + c * 8;
        soA = (uint32_t)(((m >> 1) << 3) + ((((m & 1) << 2) | c) ^ ((m >> 1) & 7))) * 16;
    }
#pragma unroll
    for (int j = 0; j < 2; j++) {
        int id = tid + j * NT, k = id >> 5, cn = id & 31;
        pB[j]  = Bp + (size_t)k * LDB + cn * 8;
        soB[j] = (uint32_t)(A_BYTES) + (uint32_t)(k * 32 + (cn ^ (k & 7))) * 16;
    }

    auto issue = [&](uint32_t stg) {
        cpa16(stg + soA, pA); pA += BK;
#pragma unroll
        for (int j = 0; j < 2; j++) { cpa16(stg + soB[j], pB[j]); pB[j] += (size_t)BK * LDB; }
    };

    float acc[2][8][4];
#pragma unroll
    for (int a = 0; a < 2; a++)
#pragma unroll
        for (int b = 0; b < 8; b++)
#pragma unroll
            for (int c = 0; c < 4; c++) acc[a][b][c] = 0.f;

#pragma unroll
    for (int p = 0; p < 5; p++) { issue(sbase + p * STG_BYTES); CP_COMMIT(); }

    // ldmatrix per-lane precomputes
    const int mat = lane >> 3, mr = lane & 7;
    const int matc = mat >> 1, matm = (mat & 1) << 3;
    uint32_t a_b8[2], a_e[2], a_hm[2];
#pragma unroll
    for (int mt = 0; mt < 2; mt++) {
        int m = wm * 32 + mt * 16 + matm + mr;
        a_b8[mt] = (uint32_t)((m >> 1) << 3);
        a_e[mt]  = (uint32_t)((m >> 1) & 7);
        a_hm[mt] = (uint32_t)((m & 1) << 2);
    }
    uint32_t b_cb[4];
#pragma unroll
    for (int ntp = 0; ntp < 4; ntp++) {
        int kb = matm + mr;
        int cn = wn * 8 + ntp * 2 + matc;
        b_cb[ntp] = (uint32_t)(kb * 32 + (cn ^ mr)) * 16;
    }

    int istage = 5, cs = 0;
    for (int kt = 0; kt < KT; kt++) {
        CP_WAIT4();
        __syncthreads();
        if (kt + 5 < KT) issue(sbase + (uint32_t)istage * STG_BYTES);
        CP_COMMIT();
        if (++istage == STAGES) istage = 0;
        const uint32_t stg = sbase + (uint32_t)cs * STG_BYTES;
        if (++cs == STAGES) cs = 0;

#pragma unroll
        for (int ks = 0; ks < 2; ks++) {
            uint32_t aF[2][4], bF[8][2];
            const uint32_t cA = (uint32_t)(ks * 2 + matc);
#pragma unroll
            for (int mt = 0; mt < 2; mt++) {
                uint32_t ch = a_b8[mt] + ((a_hm[mt] | cA) ^ a_e[mt]);
                ldsm4(aF[mt], stg + ch * 16);
            }
            const uint32_t bbase = stg + (uint32_t)A_BYTES + (uint32_t)ks * 8192u;
#pragma unroll
            for (int ntp = 0; ntp < 4; ntp++) {
                uint32_t rr[4];
                ldsm4t(rr, bbase + b_cb[ntp]);
                bF[2 * ntp][0] = rr[0];     bF[2 * ntp][1] = rr[1];
                bF[2 * ntp + 1][0] = rr[2]; bF[2 * ntp + 1][1] = rr[3];
            }
#pragma unroll
            for (int mt = 0; mt < 2; mt++)
#pragma unroll
                for (int nt = 0; nt < 8; nt++)
                    mma16(acc[mt][nt], aF[mt], bF[nt]);
        }
    }
    __syncthreads();

    // ---------------- epilogue ----------------
    __half* hpw = (__half*)g_hp4;
    float* part = g_part + (size_t)e * (B_ * DOUT_);
#pragma unroll
    for (int mt = 0; mt < 2; mt++) {
        const int r0 = m0 + wm * 32 + mt * 16 + g;   // rows r0, r0+8
        float p0 = 0.f, p1 = 0.f;
        if (MODE == 1) {
            p0 = g_probs[(size_t)r0 * NE_ + e];
            p1 = g_probs[(size_t)(r0 + 8) * NE_ + e];
        }
#pragma unroll
        for (int nt = 0; nt < 8; nt++) {
            const int c = wn * 64 + nt * 8 + 2 * t;
            if (MODE == 1) {
                float2 bv = *(const float2*)(bias + (size_t)e * DH_ + n0 + c);
                __half2 v0 = __floats2half2_rn(p0 * fmaxf(acc[mt][nt][0] + bv.x, 0.f),
                                               p0 * fmaxf(acc[mt][nt][1] + bv.y, 0.f));
                __half2 v1 = __floats2half2_rn(p1 * fmaxf(acc[mt][nt][2] + bv.x, 0.f),
                                               p1 * fmaxf(acc[mt][nt][3] + bv.y, 0.f));
                size_t base = (size_t)e * DH_ + n0 + c;
                *(__half2*)(hpw + (size_t)r0 * (NE_ * DH_) + base) = v0;
                *(__half2*)(hpw + (size_t)(r0 + 8) * (NE_ * DH_) + base) = v1;
            } else {
                *(float2*)(part + (size_t)r0 * DOUT_ + n0 + c) =
                    make_float2(acc[mt][nt][0], acc[mt][nt][1]);
                *(float2*)(part + (size_t)(r0 + 8) * DOUT_ + n0 + c) =
                    make_float2(acc[mt][nt][2], acc[mt][nt][3]);
            }
        }
    }
}

// ---------------- reduce: out = sum_q part[q] + sum_e probs*b2 ----------------
__global__ __launch_bounds__(256) void reduce_kernel(const float* __restrict__ b2,
                                                     float* __restrict__ out) {
    const int b = blockIdx.x;
    const int c = threadIdx.x * 4;
    float p[NE_];
#pragma unroll
    for (int e = 0; e < NE_; e++) p[e] = g_probs[(size_t)b * NE_ + e];
    size_t off = (size_t)b * DOUT_ + c;
    float4 a0 = *(const float4*)(g_part + off);
    float4 a1 = *(const float4*)(g_part + (size_t)B_ * DOUT_ + off);
    float4 a2 = *(const float4*)(g_part + 2 * (size_t)B_ * DOUT_ + off);
    float4 a3 = *(const float4*)(g_part + 3 * (size_t)B_ * DOUT_ + off);
    float4 r;
    r.x = (a0.x + a1.x) + (a2.x + a3.x);
    r.y = (a0.y + a1.y) + (a2.y + a3.y);
    r.z = (a0.z + a1.z) + (a2.z + a3.z);
    r.w = (a0.w + a1.w) + (a2.w + a3.w);
#pragma unroll
    for (int e = 0; e < NE_; e++) {
        float4 bv = *(const float4*)(b2 + (size_t)e * DOUT_ + c);
        r.x += p[e] * bv.x; r.y += p[e] * bv.y;
        r.z += p[e] * bv.z; r.w += p[e] * bv.w;
    }
    *(float4*)(out + off) = r;
}

// ---------------- gating / aux ----------------
__global__ void zero_kernel() {
    if (threadIdx.x < 16) g_sums[threadIdx.x] = 0.f;
}

__global__ __launch_bounds__(256) void gate_kernel(const float* __restrict__ x,
                                                   const float* __restrict__ gum,
                                                   const float* __restrict__ gw,
                                                   const float* __restrict__ gb) {
    __shared__ float psum[16];
    int tid = threadIdx.x;
    if (tid < 16) psum[tid] = 0.f;
    __syncthreads();
    int warp = tid >> 5, lane = tid & 31;
    int row = blockIdx.x * 8 + warp;

    float acc[NE_];
#pragma unroll
    for (int e = 0; e < NE_; e++) acc[e] = 0.f;
    const float* xr = x + (size_t)row * DIN_;
    for (int k = lane; k < DIN_; k += 32) {
        float xv = xr[k];
        float4 w0 = *(const float4*)(gw + (size_t)k * NE_);
        float4 w1v = *(const float4*)(gw + (size_t)k * NE_ + 4);
        acc[0] += xv * w0.x;  acc[1] += xv * w0.y;
        acc[2] += xv * w0.z;  acc[3] += xv * w0.w;
        acc[4] += xv * w1v.x; acc[5] += xv * w1v.y;
        acc[6] += xv * w1v.z; acc[7] += xv * w1v.w;
    }
#pragma unroll
    for (int e = 0; e < NE_; e++) {
#pragma unroll
        for (int off = 16; off > 0; off >>= 1)
            acc[e] += __shfl_xor_sync(0xffffffffu, acc[e], off);
    }
    if (lane == 0) {
        float s1[NE_], s2[NE_];
        float m1 = -1e30f, m2 = -1e30f;
#pragma unroll
        for (int e = 0; e < NE_; e++) {
            float lg = acc[e] + gb[e];
            s1[e] = (lg + gum[(size_t)row * NE_ + e]) * (1.0f / TAU_);
            s2[e] = lg * (1.0f / TAU_);
            m1 = fmaxf(m1, s1[e]); m2 = fmaxf(m2, s2[e]);
        }
        float d1 = 0.f, d2 = 0.f;
#pragma unroll
        for (int e = 0; e < NE_; e++) {
            s1[e] = expf(s1[e] - m1); s2[e] = expf(s2[e] - m2);
            d1 += s1[e]; d2 += s2[e];
        }
#pragma unroll
        for (int e = 0; e < NE_; e++) {
            float p = s1[e] / d1, r = s2[e] / d2;
            g_probs[(size_t)row * NE_ + e] = p;
            atomicAdd(&psum[e], p);
            atomicAdd(&psum[8 + e], r);
        }
    }
    __syncthreads();
    if (tid < 16) atomicAdd(&g_sums[tid], psum[tid]);
}

__global__ void aux_kernel(float* __restrict__ out, int out_size) {
    if (threadIdx.x != 0 || blockIdx.x != 0) return;
    float ld[NE_], imp[NE_];
    float sl = 0.f, si = 0.f;
#pragma unroll
    for (int e = 0; e < NE_; e++) {
        ld[e]  = g_sums[e] / (float)B_;
        imp[e] = g_sums[8 + e] / (float)B_;
        sl += ld[e]; si += imp[e];
    }
    float ml = sl / (float)NE_, mi = si / (float)NE_;
    float vl = 0.f, vi = 0.f, sw = 0.f;
#pragma unroll
    for (int e = 0; e < NE_; e++) {
        vl += (ld[e] - ml) * (ld[e] - ml);
        vi += (imp[e] - mi) * (imp[e] - mi);
        sw += imp[e] * ld[e];
    }
    float cvl = sqrtf(vl / (float)(NE_ - 1)) / (ml + 1e-8f);
    float cvi = sqrtf(vi / (float)(NE_ - 1)) / (mi + 1e-8f);
    out[out_size - 1] = ((float)NE_ * sw + cvi + cvl) * LAMB_;
}

// ---------------- launch ----------------
extern "C" void kernel_launch(void* const* d_in, const int* in_sizes, int n_in,
                              void* d_out, int out_size) {
    const float* x   = (const float*)d_in[0];
    const float* gum = (const float*)d_in[1];
    const float* gw  = (const float*)d_in[2];
    const float* gb  = (const float*)d_in[3];
    const float* w1  = (const float*)d_in[4];
    const float* b1  = (const float*)d_in[5];
    const float* w2  = (const float*)d_in[6];
    const float* b2  = (const float*)d_in[7];
    float* out = (float*)d_out;

    __half *xh = nullptr, *w1h = nullptr, *w2h = nullptr;
    cudaGetSymbolAddress((void**)&xh,  g_xh4);
    cudaGetSymbolAddress((void**)&w1h, g_w1h4);
    cudaGetSymbolAddress((void**)&w2h, g_w2h4);

    cudaFuncSetAttribute((const void*)gemm_h<1>,
                         cudaFuncAttributeMaxDynamicSharedMemorySize, SMEM_BYTES);
    cudaFuncSetAttribute((const void*)gemm_h<2>,
                         cudaFuncAttributeMaxDynamicSharedMemorySize, SMEM_BYTES);

    zero_kernel<<<1, 32>>>();
    half_kernel<<<2048, 256>>>(x,  xh,  (B_ * DIN_) / 4,
                               w1, w1h, (NE_ * DIN_ * DH_) / 4,
                               w2, w2h, (NE_ * DH_ * DOUT_) / 4);
    gate_kernel<<<B_ / 8, 256>>>(x, gum, gw, gb);
    gemm_h<1><<<dim3(DH_ / BN, B_ / BM, NE_), NT, SMEM_BYTES>>>(xh, w1h, b1);
    gemm_h<2><<<dim3(DOUT_ / BN, B_ / BM, KSPLIT), NT, SMEM_BYTES>>>(nullptr, w2h, nullptr);
    reduce_kernel<<<B_, 256>>>(b2, out);
    aux_kernel<<<1, 1>>>(out, out_size);
}

// round 9
// speedup vs baseline: 3.2007x; 1.0315x over previous
#include <cuda_runtime.h>
#include <cuda_fp16.h>
#include <cstdint>
#include <math.h>

#define B_    8192
#define DIN_  1024
#define DH_   2048
#define DOUT_ 1024
#define NE_   8
#define TAU_  0.8f
#define LAMB_ 0.05f

// block 128x256, 16 warps (4x4), warp tile 32x64, BK=32 halves, 6 cp.async stages
#define BM 128
#define BN 256
#define BK 32
#define NT 512
#define STAGES 6
#define A_BYTES (BM * BK * 2)         // 8192
#define B_BYTES (BK * BN * 2)         // 16384
#define STG_BYTES (A_BYTES + B_BYTES) // 24576
#define SMEM_BYTES (STAGES * STG_BYTES)
#define KSPLIT 4

// -------- scratch (__device__ globals; 16B-aligned via uint4) --------
__device__ float g_probs[(size_t)B_ * NE_];
__device__ float g_sums[16];
__device__ uint4 g_xh4[(size_t)B_ * DIN_ / 8];
__device__ uint4 g_w1h4[(size_t)NE_ * DIN_ * DH_ / 8];
__device__ uint4 g_w2h4[(size_t)NE_ * DH_ * DOUT_ / 8];
__device__ uint4 g_hp4[(size_t)B_ * NE_ * DH_ / 8];       // fp16 h' [B][E*Dh]
__device__ float g_part[(size_t)KSPLIT * B_ * DOUT_];     // split-K partials

// ---------------- helpers ----------------
__device__ __forceinline__ uint32_t smem_u32(const void* p) {
    uint32_t a;
    asm("{ .reg .u64 t; cvta.to.shared.u64 t, %1; cvt.u32.u64 %0, t; }" : "=r"(a) : "l"(p));
    return a;
}
__device__ __forceinline__ void cpa16(uint32_t dst, const void* src) {
    asm volatile("cp.async.cg.shared.global [%0], [%1], 16;" :: "r"(dst), "l"(src));
}
#define CP_COMMIT() asm volatile("cp.async.commit_group;" ::: "memory")
#define CP_WAIT4()  asm volatile("cp.async.wait_group 4;" ::: "memory")

__device__ __forceinline__ void ldsm4(uint32_t* r, uint32_t addr) {
    asm volatile("ldmatrix.sync.aligned.m8n8.x4.shared.b16 {%0,%1,%2,%3}, [%4];"
        : "=r"(r[0]), "=r"(r[1]), "=r"(r[2]), "=r"(r[3]) : "r"(addr));
}
__device__ __forceinline__ void ldsm4t(uint32_t* r, uint32_t addr) {
    asm volatile("ldmatrix.sync.aligned.m8n8.x4.trans.shared.b16 {%0,%1,%2,%3}, [%4];"
        : "=r"(r[0]), "=r"(r[1]), "=r"(r[2]), "=r"(r[3]) : "r"(addr));
}
__device__ __forceinline__ void mma16(float* c, const uint32_t* a, const uint32_t* b) {
    asm volatile(
        "mma.sync.aligned.m16n8k16.row.col.f32.f16.f16.f32 "
        "{%0,%1,%2,%3},{%4,%5,%6,%7},{%8,%9},{%0,%1,%2,%3};"
        : "+f"(c[0]), "+f"(c[1]), "+f"(c[2]), "+f"(c[3])
        : "r"(a[0]), "r"(a[1]), "r"(a[2]), "r"(a[3]), "r"(b[0]), "r"(b[1]));
}

// ---------------- prep: fp32 -> fp16 (all three tensors) ----------------
__global__ __launch_bounds__(256) void half_kernel(const float* __restrict__ s0,
                                                   __half* __restrict__ d0, int n0_,
                                                   const float* __restrict__ s1,
                                                   __half* __restrict__ d1, int n1_,
                                                   const float* __restrict__ s2,
                                                   __half* __restrict__ d2, int n2_) {
    int stride = gridDim.x * 256;
    int t0 = blockIdx.x * 256 + threadIdx.x;
    for (int i = t0; i < n0_; i += stride) {
        float4 v = ((const float4*)s0)[i];
        ((__half2*)d0)[2 * i]     = __floats2half2_rn(v.x, v.y);
        ((__half2*)d0)[2 * i + 1] = __floats2half2_rn(v.z, v.w);
    }
    for (int i = t0; i < n1_; i += stride) {
        float4 v = ((const float4*)s1)[i];
        ((__half2*)d1)[2 * i]     = __floats2half2_rn(v.x, v.y);
        ((__half2*)d1)[2 * i + 1] = __floats2half2_rn(v.z, v.w);
    }
    for (int i = t0; i < n2_; i += stride) {
        float4 v = ((const float4*)s2)[i];
        ((__half2*)d2)[2 * i]     = __floats2half2_rn(v.x, v.y);
        ((__half2*)d2)[2 * i + 1] = __floats2half2_rn(v.z, v.w);
    }
}

// ---------------- main GEMM (fp16 in, fp32 accum), 512 threads ----------------
// MODE 1: h' = fp16(probs * relu(xh @ w1h + b1)), grid.z = expert, KT=32
// MODE 2: part[kq] = hp slice @ w2h slice, grid.z = kq, KT=128
template <int MODE>
__global__ __launch_bounds__(NT, 1) void gemm_h(const __half* __restrict__ Aglob,
                                                const __half* __restrict__ Bglob,
                                                const float* __restrict__ bias) {
    constexpr int KT  = (MODE == 1) ? (DIN_ / BK) : (NE_ * DH_ / BK / KSPLIT);
    constexpr int LDA = (MODE == 1) ? DIN_ : (NE_ * DH_);
    constexpr int LDB = (MODE == 1) ? DH_ : DOUT_;

    extern __shared__ float sm[];
    const int tid  = threadIdx.x;
    const int lane = tid & 31, warp = tid >> 5;
    const int g = lane >> 2, t = lane & 3;
    const int wm = warp >> 2, wn = warp & 3;     // 4x4 warps, warp tile 32x64

    const int e  = blockIdx.z;                   // expert (MODE1) or kq (MODE2)
    const int m0 = blockIdx.y * BM;
    const int n0 = blockIdx.x * BN;
    const __half* hp = (const __half*)g_hp4;
    const __half* Ap = (MODE == 1) ? (Aglob + (size_t)m0 * LDA)
                                   : (hp + (size_t)m0 * LDA + (size_t)e * (NE_ * DH_ / KSPLIT));
    const __half* Bp = (MODE == 1)
        ? (Bglob + (size_t)e * DIN_ * DH_ + n0)
        : (Bglob + (size_t)e * (NE_ * DH_ / KSPLIT) * LDB + n0);
    const uint32_t sbase = smem_u32(sm);

    // copy descriptors
    const __half* pA; uint32_t soA;
    const __half* pB[2]; uint32_t soB[2];
    {
        int m = tid >> 2, c = tid & 3;
        pA  = Ap + (size_t)m * LDA + c * 8;
        soA = (uint32_t)(((m >> 1) << 3) + ((((m & 1) << 2) | c) ^ ((m >> 1) & 7))) * 16;
    }
#pragma unroll
    for (int j = 0; j < 2; j++) {
        int id = tid + j * NT, k = id >> 5, cn = id & 31;
        pB[j]  = Bp + (size_t)k * LDB + cn * 8;
        soB[j] = (uint32_t)(A_BYTES) + (uint32_t)(k * 32 + (cn ^ (k & 7))) * 16;
    }

    auto issue = [&](uint32_t stg) {
        cpa16(stg + soA, pA); pA += BK;
#pragma unroll
        for (int j = 0; j < 2; j++) { cpa16(stg + soB[j], pB[j]); pB[j] += (size_t)BK * LDB; }
    };

    float acc[2][8][4];
#pragma unroll
    for (int a = 0; a < 2; a++)
#pragma unroll
        for (int b = 0; b < 8; b++)
#pragma unroll
            for (int c = 0; c < 4; c++) acc[a][b][c] = 0.f;

#pragma unroll
    for (int p = 0; p < 5; p++) { issue(sbase + p * STG_BYTES); CP_COMMIT(); }

    // ldmatrix per-lane precomputes
    const int mat = lane >> 3, mr = lane & 7;
    const int matc = mat >> 1, matm = (mat & 1) << 3;
    uint32_t a_b8[2], a_e[2], a_hm[2];
#pragma unroll
    for (int mt = 0; mt < 2; mt++) {
        int m = wm * 32 + mt * 16 + matm + mr;
        a_b8[mt] = (uint32_t)((m >> 1) << 3);
        a_e[mt]  = (uint32_t)((m >> 1) & 7);
        a_hm[mt] = (uint32_t)((m & 1) << 2);
    }
    uint32_t b_cb[4];
#pragma unroll
    for (int ntp = 0; ntp < 4; ntp++) {
        int kb = matm + mr;
        int cn = wn * 8 + ntp * 2 + matc;
        b_cb[ntp] = (uint32_t)(kb * 32 + (cn ^ mr)) * 16;
    }

    uint32_t aF[2][2][4], bF[2][8][2];

    auto load_frag = [&](uint32_t stg, int ks, int buf) {
        const uint32_t cA = (uint32_t)(ks * 2 + matc);
#pragma unroll
        for (int mt = 0; mt < 2; mt++) {
            uint32_t ch = a_b8[mt] + ((a_hm[mt] | cA) ^ a_e[mt]);
            ldsm4(aF[buf][mt], stg + ch * 16);
        }
        const uint32_t bbase = stg + (uint32_t)A_BYTES + (uint32_t)ks * 8192u;
#pragma unroll
        for (int ntp = 0; ntp < 4; ntp++) {
            uint32_t rr[4];
            ldsm4t(rr, bbase + b_cb[ntp]);
            bF[buf][2 * ntp][0] = rr[0];     bF[buf][2 * ntp][1] = rr[1];
            bF[buf][2 * ntp + 1][0] = rr[2]; bF[buf][2 * ntp + 1][1] = rr[3];
        }
    };

    int istage = 5, cs = 0;
    for (int kt = 0; kt < KT; kt++) {
        CP_WAIT4();
        __syncthreads();
        const uint32_t stg = sbase + (uint32_t)cs * STG_BYTES;
        if (++cs == STAGES) cs = 0;

        load_frag(stg, 0, 0);                                  // ks0 frags first
        if (kt + 5 < KT) issue(sbase + (uint32_t)istage * STG_BYTES);  // overlap LDSM latency
        CP_COMMIT();
        if (++istage == STAGES) istage = 0;

        load_frag(stg, 1, 1);                                  // ks1 LDSM under ks0 MMAs
#pragma unroll
        for (int mt = 0; mt < 2; mt++)
#pragma unroll
            for (int nt = 0; nt < 8; nt++)
                mma16(acc[mt][nt], aF[0][mt], bF[0][nt]);
#pragma unroll
        for (int mt = 0; mt < 2; mt++)
#pragma unroll
            for (int nt = 0; nt < 8; nt++)
                mma16(acc[mt][nt], aF[1][mt], bF[1][nt]);
    }
    __syncthreads();

    // ---------------- epilogue ----------------
    __half* hpw = (__half*)g_hp4;
    float* part = g_part + (size_t)e * (B_ * DOUT_);
#pragma unroll
    for (int mt = 0; mt < 2; mt++) {
        const int r0 = m0 + wm * 32 + mt * 16 + g;   // rows r0, r0+8
        float p0 = 0.f, p1 = 0.f;
        if (MODE == 1) {
            p0 = g_probs[(size_t)r0 * NE_ + e];
            p1 = g_probs[(size_t)(r0 + 8) * NE_ + e];
        }
#pragma unroll
        for (int nt = 0; nt < 8; nt++) {
            const int c = wn * 64 + nt * 8 + 2 * t;
            if (MODE == 1) {
                float2 bv = *(const float2*)(bias + (size_t)e * DH_ + n0 + c);
                __half2 v0 = __floats2half2_rn(p0 * fmaxf(acc[mt][nt][0] + bv.x, 0.f),
                                               p0 * fmaxf(acc[mt][nt][1] + bv.y, 0.f));
                __half2 v1 = __floats2half2_rn(p1 * fmaxf(acc[mt][nt][2] + bv.x, 0.f),
                                               p1 * fmaxf(acc[mt][nt][3] + bv.y, 0.f));
                size_t base = (size_t)e * DH_ + n0 + c;
                *(__half2*)(hpw + (size_t)r0 * (NE_ * DH_) + base) = v0;
                *(__half2*)(hpw + (size_t)(r0 + 8) * (NE_ * DH_) + base) = v1;
            } else {
                *(float2*)(part + (size_t)r0 * DOUT_ + n0 + c) =
                    make_float2(acc[mt][nt][0], acc[mt][nt][1]);
                *(float2*)(part + (size_t)(r0 + 8) * DOUT_ + n0 + c) =
                    make_float2(acc[mt][nt][2], acc[mt][nt][3]);
            }
        }
    }
}

// ---------------- reduce: out = sum_q part[q] + sum_e probs*b2 ----------------
__global__ __launch_bounds__(256) void reduce_kernel(const float* __restrict__ b2,
                                                     float* __restrict__ out) {
    const int b = blockIdx.x;
    const int c = threadIdx.x * 4;
    float p[NE_];
#pragma unroll
    for (int e = 0; e < NE_; e++) p[e] = g_probs[(size_t)b * NE_ + e];
    size_t off = (size_t)b * DOUT_ + c;
    float4 a0 = *(const float4*)(g_part + off);
    float4 a1 = *(const float4*)(g_part + (size_t)B_ * DOUT_ + off);
    float4 a2 = *(const float4*)(g_part + 2 * (size_t)B_ * DOUT_ + off);
    float4 a3 = *(const float4*)(g_part + 3 * (size_t)B_ * DOUT_ + off);
    float4 r;
    r.x = (a0.x + a1.x) + (a2.x + a3.x);
    r.y = (a0.y + a1.y) + (a2.y + a3.y);
    r.z = (a0.z + a1.z) + (a2.z + a3.z);
    r.w = (a0.w + a1.w) + (a2.w + a3.w);
#pragma unroll
    for (int e = 0; e < NE_; e++) {
        float4 bv = *(const float4*)(b2 + (size_t)e * DOUT_ + c);
        r.x += p[e] * bv.x; r.y += p[e] * bv.y;
        r.z += p[e] * bv.z; r.w += p[e] * bv.w;
    }
    *(float4*)(out + off) = r;
}

// ---------------- gating / aux ----------------
__global__ void zero_kernel() {
    if (threadIdx.x < 16) g_sums[threadIdx.x] = 0.f;
}

__global__ __launch_bounds__(256) void gate_kernel(const float* __restrict__ x,
                                                   const float* __restrict__ gum,
                                                   const float* __restrict__ gw,
                                                   const float* __restrict__ gb) {
    __shared__ float psum[16];
    int tid = threadIdx.x;
    if (tid < 16) psum[tid] = 0.f;
    __syncthreads();
    int warp = tid >> 5, lane = tid & 31;
    int row = blockIdx.x * 8 + warp;

    float acc[NE_];
#pragma unroll
    for (int e = 0; e < NE_; e++) acc[e] = 0.f;
    const float* xr = x + (size_t)row * DIN_;
    for (int k = lane; k < DIN_; k += 32) {
        float xv = xr[k];
        float4 w0 = *(const float4*)(gw + (size_t)k * NE_);
        float4 w1v = *(const float4*)(gw + (size_t)k * NE_ + 4);
        acc[0] += xv * w0.x;  acc[1] += xv * w0.y;
        acc[2] += xv * w0.z;  acc[3] += xv * w0.w;
        acc[4] += xv * w1v.x; acc[5] += xv * w1v.y;
        acc[6] += xv * w1v.z; acc[7] += xv * w1v.w;
    }
#pragma unroll
    for (int e = 0; e < NE_; e++) {
#pragma unroll
        for (int off = 16; off > 0; off >>= 1)
            acc[e] += __shfl_xor_sync(0xffffffffu, acc[e], off);
    }
    if (lane == 0) {
        float s1[NE_], s2[NE_];
        float m1 = -1e30f, m2 = -1e30f;
#pragma unroll
        for (int e = 0; e < NE_; e++) {
            float lg = acc[e] + gb[e];
            s1[e] = (lg + gum[(size_t)row * NE_ + e]) * (1.0f / TAU_);
            s2[e] = lg * (1.0f / TAU_);
            m1 = fmaxf(m1, s1[e]); m2 = fmaxf(m2, s2[e]);
        }
        float d1 = 0.f, d2 = 0.f;
#pragma unroll
        for (int e = 0; e < NE_; e++) {
            s1[e] = expf(s1[e] - m1); s2[e] = expf(s2[e] - m2);
            d1 += s1[e]; d2 += s2[e];
        }
#pragma unroll
        for (int e = 0; e < NE_; e++) {
            float p = s1[e] / d1, r = s2[e] / d2;
            g_probs[(size_t)row * NE_ + e] = p;
            atomicAdd(&psum[e], p);
            atomicAdd(&psum[8 + e], r);
        }
    }
    __syncthreads();
    if (tid < 16) atomicAdd(&g_sums[tid], psum[tid]);
}

__global__ void aux_kernel(float* __restrict__ out, int out_size) {
    if (threadIdx.x != 0 || blockIdx.x != 0) return;
    float ld[NE_], imp[NE_];
    float sl = 0.f, si = 0.f;
#pragma unroll
    for (int e = 0; e < NE_; e++) {
        ld[e]  = g_sums[e] / (float)B_;
        imp[e] = g_sums[8 + e] / (float)B_;
        sl += ld[e]; si += imp[e];
    }
    float ml = sl / (float)NE_, mi = si / (float)NE_;
    float vl = 0.f, vi = 0.f, sw = 0.f;
#pragma unroll
    for (int e = 0; e < NE_; e++) {
        vl += (ld[e] - ml) * (ld[e] - ml);
        vi += (imp[e] - mi) * (imp[e] - mi);
        sw += imp[e] * ld[e];
    }
    float cvl = sqrtf(vl / (float)(NE_ - 1)) / (ml + 1e-8f);
    float cvi = sqrtf(vi / (float)(NE_ - 1)) / (mi + 1e-8f);
    out[out_size - 1] = ((float)NE_ * sw + cvi + cvl) * LAMB_;
}

// ---------------- launch ----------------
extern "C" void kernel_launch(void* const* d_in, const int* in_sizes, int n_in,
                              void* d_out, int out_size) {
    const float* x   = (const float*)d_in[0];
    const float* gum = (const float*)d_in[1];
    const float* gw  = (const float*)d_in[2];
    const float* gb  = (const float*)d_in[3];
    const float* w1  = (const float*)d_in[4];
    const float* b1  = (const float*)d_in[5];
    const float* w2  = (const float*)d_in[6];
    const float* b2  = (const float*)d_in[7];
    float* out = (float*)d_out;

    __half *xh = nullptr, *w1h = nullptr, *w2h = nullptr;
    cudaGetSymbolAddress((void**)&xh,  g_xh4);
    cudaGetSymbolAddress((void**)&w1h, g_w1h4);
    cudaGetSymbolAddress((void**)&w2h, g_w2h4);

    cudaFuncSetAttribute((const void*)gemm_h<1>,
                         cudaFuncAttributeMaxDynamicSharedMemorySize, SMEM_BYTES);
    cudaFuncSetAttribute((const void*)gemm_h<2>,
                         cudaFuncAttributeMaxDynamicSharedMemorySize, SMEM_BYTES);

    zero_kernel<<<1, 32>>>();
    half_kernel<<<2048, 256>>>(x,  xh,  (B_ * DIN_) / 4,
                               w1, w1h, (NE_ * DIN_ * DH_) / 4,
                               w2, w2h, (NE_ * DH_ * DOUT_) / 4);
    gate_kernel<<<B_ / 8, 256>>>(x, gum, gw, gb);
    gemm_h<1><<<dim3(DH_ / BN, B_ / BM, NE_), NT, SMEM_BYTES>>>(xh, w1h, b1);
    gemm_h<2><<<dim3(DOUT_ / BN, B_ / BM, KSPLIT), NT, SMEM_BYTES>>>(nullptr, w2h, nullptr);
    reduce_kernel<<<B_, 256>>>(b2, out);
    aux_kernel<<<1, 1>>>(out, out_size);
}

// round 10
// speedup vs baseline: 3.2650x; 1.0201x over previous
#include <cuda_runtime.h>
#include <cuda_fp16.h>
#include <cstdint>
#include <math.h>

#define B_    8192
#define DIN_  1024
#define DH_   2048
#define DOUT_ 1024
#define NE_   8
#define TAU_  0.8f
#define LAMB_ 0.05f

// block 128x128, 8 warps (4x2), warp tile 32x64, BK=32 halves, 6 stages, 2 CTAs/SM
#define BM 128
#define BN 128
#define BK 32
#define NT 256
#define STAGES 6
#define A_BYTES (BM * BK * 2)         // 8192
#define B_BYTES (BK * BN * 2)         // 8192
#define STG_BYTES (A_BYTES + B_BYTES) // 16384
#define SMEM_BYTES (STAGES * STG_BYTES)  // 98304
#define KSPLIT 4

// -------- scratch (__device__ globals; 16B-aligned via uint4) --------
__device__ float g_probs[(size_t)B_ * NE_];
__device__ float g_sums[16];
__device__ uint4 g_xh4[(size_t)B_ * DIN_ / 8];
__device__ uint4 g_w1h4[(size_t)NE_ * DIN_ * DH_ / 8];
__device__ uint4 g_w2h4[(size_t)NE_ * DH_ * DOUT_ / 8];
__device__ uint4 g_hp4[(size_t)B_ * NE_ * DH_ / 8];       // fp16 h' [B][E*Dh]
__device__ float g_part[(size_t)KSPLIT * B_ * DOUT_];     // split-K partials

// ---------------- helpers ----------------
__device__ __forceinline__ uint32_t smem_u32(const void* p) {
    uint32_t a;
    asm("{ .reg .u64 t; cvta.to.shared.u64 t, %1; cvt.u32.u64 %0, t; }" : "=r"(a) : "l"(p));
    return a;
}
__device__ __forceinline__ void cpa16(uint32_t dst, const void* src) {
    asm volatile("cp.async.cg.shared.global [%0], [%1], 16;" :: "r"(dst), "l"(src));
}
#define CP_COMMIT() asm volatile("cp.async.commit_group;" ::: "memory")
#define CP_WAIT4()  asm volatile("cp.async.wait_group 4;" ::: "memory")

__device__ __forceinline__ void ldsm4(uint32_t* r, uint32_t addr) {
    asm volatile("ldmatrix.sync.aligned.m8n8.x4.shared.b16 {%0,%1,%2,%3}, [%4];"
        : "=r"(r[0]), "=r"(r[1]), "=r"(r[2]), "=r"(r[3]) : "r"(addr));
}
__device__ __forceinline__ void ldsm4t(uint32_t* r, uint32_t addr) {
    asm volatile("ldmatrix.sync.aligned.m8n8.x4.trans.shared.b16 {%0,%1,%2,%3}, [%4];"
        : "=r"(r[0]), "=r"(r[1]), "=r"(r[2]), "=r"(r[3]) : "r"(addr));
}
__device__ __forceinline__ void mma16(float* c, const uint32_t* a, const uint32_t* b) {
    asm volatile(
        "mma.sync.aligned.m16n8k16.row.col.f32.f16.f16.f32 "
        "{%0,%1,%2,%3},{%4,%5,%6,%7},{%8,%9},{%0,%1,%2,%3};"
        : "+f"(c[0]), "+f"(c[1]), "+f"(c[2]), "+f"(c[3])
        : "r"(a[0]), "r"(a[1]), "r"(a[2]), "r"(a[3]), "r"(b[0]), "r"(b[1]));
}

// ---------------- prep: fp32 -> fp16 (all three tensors) ----------------
__global__ __launch_bounds__(256) void half_kernel(const float* __restrict__ s0,
                                                   __half* __restrict__ d0, int n0_,
                                                   const float* __restrict__ s1,
                                                   __half* __restrict__ d1, int n1_,
                                                   const float* __restrict__ s2,
                                                   __half* __restrict__ d2, int n2_) {
    int stride = gridDim.x * 256;
    int t0 = blockIdx.x * 256 + threadIdx.x;
    for (int i = t0; i < n0_; i += stride) {
        float4 v = ((const float4*)s0)[i];
        ((__half2*)d0)[2 * i]     = __floats2half2_rn(v.x, v.y);
        ((__half2*)d0)[2 * i + 1] = __floats2half2_rn(v.z, v.w);
    }
    for (int i = t0; i < n1_; i += stride) {
        float4 v = ((const float4*)s1)[i];
        ((__half2*)d1)[2 * i]     = __floats2half2_rn(v.x, v.y);
        ((__half2*)d1)[2 * i + 1] = __floats2half2_rn(v.z, v.w);
    }
    for (int i = t0; i < n2_; i += stride) {
        float4 v = ((const float4*)s2)[i];
        ((__half2*)d2)[2 * i]     = __floats2half2_rn(v.x, v.y);
        ((__half2*)d2)[2 * i + 1] = __floats2half2_rn(v.z, v.w);
    }
}

// ---------------- main GEMM (fp16 in, fp32 accum), 256 threads, 2 CTAs/SM ----------------
// MODE 1: h' = fp16(probs * relu(xh @ w1h + b1)), grid.z = expert, KT=32
// MODE 2: part[kq] = hp slice @ w2h slice, grid.z = kq, KT=128
template <int MODE>
__global__ __launch_bounds__(NT, 2) void gemm_h(const __half* __restrict__ Aglob,
                                                const __half* __restrict__ Bglob,
                                                const float* __restrict__ bias) {
    constexpr int KT  = (MODE == 1) ? (DIN_ / BK) : (NE_ * DH_ / BK / KSPLIT);
    constexpr int LDA = (MODE == 1) ? DIN_ : (NE_ * DH_);
    constexpr int LDB = (MODE == 1) ? DH_ : DOUT_;

    extern __shared__ float sm[];
    const int tid  = threadIdx.x;
    const int lane = tid & 31, warp = tid >> 5;
    const int g = lane >> 2, t = lane & 3;
    const int wm = warp >> 1, wn = warp & 1;     // 4x2 warps, warp tile 32x64

    const int e  = blockIdx.z;                   // expert (MODE1) or kq (MODE2)
    const int m0 = blockIdx.y * BM;
    const int n0 = blockIdx.x * BN;
    const __half* hp = (const __half*)g_hp4;
    const __half* Ap = (MODE == 1) ? (Aglob + (size_t)m0 * LDA)
                                   : (hp + (size_t)m0 * LDA + (size_t)e * (NE_ * DH_ / KSPLIT));
    const __half* Bp = (MODE == 1)
        ? (Bglob + (size_t)e * DIN_ * DH_ + n0)
        : (Bglob + (size_t)e * (NE_ * DH_ / KSPLIT) * LDB + n0);
    const uint32_t sbase = smem_u32(sm);

    // copy descriptors: A 512 chunks (2/thr), B 512 chunks (2/thr)
    // A phys chunk(m,c) = (m>>1)*8 + ((((m&1)<<2)|c) ^ ((m>>1)&7)),  c = chunk-in-row (0..3)
    // B phys chunk(k,cn) = k*16 + (cn ^ (k&7)),                      cn = chunk-in-row (0..15)
    const __half* pA[2]; uint32_t soA[2];
    const __half* pB[2]; uint32_t soB[2];
#pragma unroll
    for (int j = 0; j < 2; j++) {
        int id = tid + j * NT, m = id >> 2, c = id & 3;
        pA[j]  = Ap + (size_t)m * LDA + c * 8;
        soA[j] = (uint32_t)(((m >> 1) << 3) + ((((m & 1) << 2) | c) ^ ((m >> 1) & 7))) * 16;
    }
#pragma unroll
    for (int j = 0; j < 2; j++) {
        int id = tid + j * NT, k = id >> 4, cn = id & 15;
        pB[j]  = Bp + (size_t)k * LDB + cn * 8;
        soB[j] = (uint32_t)(A_BYTES) + (uint32_t)(k * 16 + (cn ^ (k & 7))) * 16;
    }

    auto issue = [&](uint32_t stg) {
#pragma unroll
        for (int j = 0; j < 2; j++) { cpa16(stg + soA[j], pA[j]); pA[j] += BK; }
#pragma unroll
        for (int j = 0; j < 2; j++) { cpa16(stg + soB[j], pB[j]); pB[j] += (size_t)BK * LDB; }
    };

    float acc[2][8][4];
#pragma unroll
    for (int a = 0; a < 2; a++)
#pragma unroll
        for (int b = 0; b < 8; b++)
#pragma unroll
            for (int c = 0; c < 4; c++) acc[a][b][c] = 0.f;

#pragma unroll
    for (int p = 0; p < 5; p++) { issue(sbase + p * STG_BYTES); CP_COMMIT(); }

    // ldmatrix per-lane precomputes
    const int mat = lane >> 3, mr = lane & 7;
    const int matc = mat >> 1, matm = (mat & 1) << 3;
    uint32_t a_b8[2], a_e[2], a_hm[2];
#pragma unroll
    for (int mt = 0; mt < 2; mt++) {
        int m = wm * 32 + mt * 16 + matm + mr;
        a_b8[mt] = (uint32_t)((m >> 1) << 3);
        a_e[mt]  = (uint32_t)((m >> 1) & 7);
        a_hm[mt] = (uint32_t)((m & 1) << 2);
    }
    uint32_t b_cb[4];
#pragma unroll
    for (int ntp = 0; ntp < 4; ntp++) {
        int kb = matm + mr;                    // row within 16-row half-tile
        int cn = wn * 8 + ntp * 2 + matc;      // chunk-in-row
        b_cb[ntp] = (uint32_t)(kb * 16 + (cn ^ mr)) * 16;
    }

    int istage = 5, cs = 0;
    for (int kt = 0; kt < KT; kt++) {
        CP_WAIT4();
        __syncthreads();
        const uint32_t stg = sbase + (uint32_t)cs * STG_BYTES;
        if (++cs == STAGES) cs = 0;

        uint32_t aF[2][4], bF[8][2];
        // ks = 0 frags first; overlap their LDSM latency with LDGSTS issue
        {
            const uint32_t cA = (uint32_t)matc;
#pragma unroll
            for (int mt = 0; mt < 2; mt++) {
                uint32_t ch = a_b8[mt] + ((a_hm[mt] | cA) ^ a_e[mt]);
                ldsm4(aF[mt], stg + ch * 16);
            }
            const uint32_t bbase = stg + (uint32_t)A_BYTES;
#pragma unroll
            for (int ntp = 0; ntp < 4; ntp++) {
                uint32_t rr[4];
                ldsm4t(rr, bbase + b_cb[ntp]);
                bF[2 * ntp][0] = rr[0];     bF[2 * ntp][1] = rr[1];
                bF[2 * ntp + 1][0] = rr[2]; bF[2 * ntp + 1][1] = rr[3];
            }
        }
        if (kt + 5 < KT) issue(sbase + (uint32_t)istage * STG_BYTES);
        CP_COMMIT();
        if (++istage == STAGES) istage = 0;

#pragma unroll
        for (int mt = 0; mt < 2; mt++)
#pragma unroll
            for (int nt = 0; nt < 8; nt++)
                mma16(acc[mt][nt], aF[mt], bF[nt]);

        // ks = 1
        {
            const uint32_t cA = (uint32_t)(2 + matc);
#pragma unroll
            for (int mt = 0; mt < 2; mt++) {
                uint32_t ch = a_b8[mt] + ((a_hm[mt] | cA) ^ a_e[mt]);
                ldsm4(aF[mt], stg + ch * 16);
            }
            const uint32_t bbase = stg + (uint32_t)A_BYTES + 4096u;  // rows 16..31
#pragma unroll
            for (int ntp = 0; ntp < 4; ntp++) {
                uint32_t rr[4];
                ldsm4t(rr, bbase + b_cb[ntp]);
                bF[2 * ntp][0] = rr[0];     bF[2 * ntp][1] = rr[1];
                bF[2 * ntp + 1][0] = rr[2]; bF[2 * ntp + 1][1] = rr[3];
            }
        }
#pragma unroll
        for (int mt = 0; mt < 2; mt++)
#pragma unroll
            for (int nt = 0; nt < 8; nt++)
                mma16(acc[mt][nt], aF[mt], bF[nt]);
    }
    __syncthreads();

    // ---------------- epilogue ----------------
    __half* hpw = (__half*)g_hp4;
    float* part = g_part + (size_t)e * (B_ * DOUT_);
#pragma unroll
    for (int mt = 0; mt < 2; mt++) {
        const int r0 = m0 + wm * 32 + mt * 16 + g;   // rows r0, r0+8
        float p0 = 0.f, p1 = 0.f;
        if (MODE == 1) {
            p0 = g_probs[(size_t)r0 * NE_ + e];
            p1 = g_probs[(size_t)(r0 + 8) * NE_ + e];
        }
#pragma unroll
        for (int nt = 0; nt < 8; nt++) {
            const int c = wn * 64 + nt * 8 + 2 * t;
            if (MODE == 1) {
                float2 bv = *(const float2*)(bias + (size_t)e * DH_ + n0 + c);
                __half2 v0 = __floats2half2_rn(p0 * fmaxf(acc[mt][nt][0] + bv.x, 0.f),
                                               p0 * fmaxf(acc[mt][nt][1] + bv.y, 0.f));
                __half2 v1 = __floats2half2_rn(p1 * fmaxf(acc[mt][nt][2] + bv.x, 0.f),
                                               p1 * fmaxf(acc[mt][nt][3] + bv.y, 0.f));
                size_t base = (size_t)e * DH_ + n0 + c;
                *(__half2*)(hpw + (size_t)r0 * (NE_ * DH_) + base) = v0;
                *(__half2*)(hpw + (size_t)(r0 + 8) * (NE_ * DH_) + base) = v1;
            } else {
                *(float2*)(part + (size_t)r0 * DOUT_ + n0 + c) =
                    make_float2(acc[mt][nt][0], acc[mt][nt][1]);
                *(float2*)(part + (size_t)(r0 + 8) * DOUT_ + n0 + c) =
                    make_float2(acc[mt][nt][2], acc[mt][nt][3]);
            }
        }
    }
}

// ---------------- reduce: out = sum_q part[q] + sum_e probs*b2 ----------------
__global__ __launch_bounds__(256) void reduce_kernel(const float* __restrict__ b2,
                                                     float* __restrict__ out) {
    const int b = blockIdx.x;
    const int c = threadIdx.x * 4;
    float p[NE_];
#pragma unroll
    for (int e = 0; e < NE_; e++) p[e] = g_probs[(size_t)b * NE_ + e];
    size_t off = (size_t)b * DOUT_ + c;
    float4 a0 = *(const float4*)(g_part + off);
    float4 a1 = *(const float4*)(g_part + (size_t)B_ * DOUT_ + off);
    float4 a2 = *(const float4*)(g_part + 2 * (size_t)B_ * DOUT_ + off);
    float4 a3 = *(const float4*)(g_part + 3 * (size_t)B_ * DOUT_ + off);
    float4 r;
    r.x = (a0.x + a1.x) + (a2.x + a3.x);
    r.y = (a0.y + a1.y) + (a2.y + a3.y);
    r.z = (a0.z + a1.z) + (a2.z + a3.z);
    r.w = (a0.w + a1.w) + (a2.w + a3.w);
#pragma unroll
    for (int e = 0; e < NE_; e++) {
        float4 bv = *(const float4*)(b2 + (size_t)e * DOUT_ + c);
        r.x += p[e] * bv.x; r.y += p[e] * bv.y;
        r.z += p[e] * bv.z; r.w += p[e] * bv.w;
    }
    *(float4*)(out + off) = r;
}

// ---------------- gating / aux ----------------
__global__ void zero_kernel() {
    if (threadIdx.x < 16) g_sums[threadIdx.x] = 0.f;
}

__global__ __launch_bounds__(256) void gate_kernel(const float* __restrict__ x,
                                                   const float* __restrict__ gum,
                                                   const float* __restrict__ gw,
                                                   const float* __restrict__ gb) {
    __shared__ float psum[16];
    int tid = threadIdx.x;
    if (tid < 16) psum[tid] = 0.f;
    __syncthreads();
    int warp = tid >> 5, lane = tid & 31;
    int row = blockIdx.x * 8 + warp;

    float acc[NE_];
#pragma unroll
    for (int e = 0; e < NE_; e++) acc[e] = 0.f;
    const float* xr = x + (size_t)row * DIN_;
    for (int k = lane; k < DIN_; k += 32) {
        float xv = xr[k];
        float4 w0 = *(const float4*)(gw + (size_t)k * NE_);
        float4 w1v = *(const float4*)(gw + (size_t)k * NE_ + 4);
        acc[0] += xv * w0.x;  acc[1] += xv * w0.y;
        acc[2] += xv * w0.z;  acc[3] += xv * w0.w;
        acc[4] += xv * w1v.x; acc[5] += xv * w1v.y;
        acc[6] += xv * w1v.z; acc[7] += xv * w1v.w;
    }
#pragma unroll
    for (int e = 0; e < NE_; e++) {
#pragma unroll
        for (int off = 16; off > 0; off >>= 1)
            acc[e] += __shfl_xor_sync(0xffffffffu, acc[e], off);
    }
    if (lane == 0) {
        float s1[NE_], s2[NE_];
        float m1 = -1e30f, m2 = -1e30f;
#pragma unroll
        for (int e = 0; e < NE_; e++) {
            float lg = acc[e] + gb[e];
            s1[e] = (lg + gum[(size_t)row * NE_ + e]) * (1.0f / TAU_);
            s2[e] = lg * (1.0f / TAU_);
            m1 = fmaxf(m1, s1[e]); m2 = fmaxf(m2, s2[e]);
        }
        float d1 = 0.f, d2 = 0.f;
#pragma unroll
        for (int e = 0; e < NE_; e++) {
            s1[e] = expf(s1[e] - m1); s2[e] = expf(s2[e] - m2);
            d1 += s1[e]; d2 += s2[e];
        }
#pragma unroll
        for (int e = 0; e < NE_; e++) {
            float p = s1[e] / d1, r = s2[e] / d2;
            g_probs[(size_t)row * NE_ + e] = p;
            atomicAdd(&psum[e], p);
            atomicAdd(&psum[8 + e], r);
        }
    }
    __syncthreads();
    if (tid < 16) atomicAdd(&g_sums[tid], psum[tid]);
}

__global__ void aux_kernel(float* __restrict__ out, int out_size) {
    if (threadIdx.x != 0 || blockIdx.x != 0) return;
    float ld[NE_], imp[NE_];
    float sl = 0.f, si = 0.f;
#pragma unroll
    for (int e = 0; e < NE_; e++) {
        ld[e]  = g_sums[e] / (float)B_;
        imp[e] = g_sums[8 + e] / (float)B_;
        sl += ld[e]; si += imp[e];
    }
    float ml = sl / (float)NE_, mi = si / (float)NE_;
    float vl = 0.f, vi = 0.f, sw = 0.f;
#pragma unroll
    for (int e = 0; e < NE_; e++) {
        vl += (ld[e] - ml) * (ld[e] - ml);
        vi += (imp[e] - mi) * (imp[e] - mi);
        sw += imp[e] * ld[e];
    }
    float cvl = sqrtf(vl / (float)(NE_ - 1)) / (ml + 1e-8f);
    float cvi = sqrtf(vi / (float)(NE_ - 1)) / (mi + 1e-8f);
    out[out_size - 1] = ((float)NE_ * sw + cvi + cvl) * LAMB_;
}

// ---------------- launch ----------------
extern "C" void kernel_launch(void* const* d_in, const int* in_sizes, int n_in,
                              void* d_out, int out_size) {
    const float* x   = (const float*)d_in[0];
    const float* gum = (const float*)d_in[1];
    const float* gw  = (const float*)d_in[2];
    const float* gb  = (const float*)d_in[3];
    const float* w1  = (const float*)d_in[4];
    const float* b1  = (const float*)d_in[5];
    const float* w2  = (const float*)d_in[6];
    const float* b2  = (const float*)d_in[7];
    float* out = (float*)d_out;

    __half *xh = nullptr, *w1h = nullptr, *w2h = nullptr;
    cudaGetSymbolAddress((void**)&xh,  g_xh4);
    cudaGetSymbolAddress((void**)&w1h, g_w1h4);
    cudaGetSymbolAddress((void**)&w2h, g_w2h4);

    cudaFuncSetAttribute((const void*)gemm_h<1>,
                         cudaFuncAttributeMaxDynamicSharedMemorySize, SMEM_BYTES);
    cudaFuncSetAttribute((const void*)gemm_h<2>,
                         cudaFuncAttributeMaxDynamicSharedMemorySize, SMEM_BYTES);

    zero_kernel<<<1, 32>>>();
    half_kernel<<<2048, 256>>>(x,  xh,  (B_ * DIN_) / 4,
                               w1, w1h, (NE_ * DIN_ * DH_) / 4,
                               w2, w2h, (NE_ * DH_ * DOUT_) / 4);
    gate_kernel<<<B_ / 8, 256>>>(x, gum, gw, gb);
    gemm_h<1><<<dim3(DH_ / BN, B_ / BM, NE_), NT, SMEM_BYTES>>>(xh, w1h, b1);
    gemm_h<2><<<dim3(DOUT_ / BN, B_ / BM, KSPLIT), NT, SMEM_BYTES>>>(nullptr, w2h, nullptr);
    reduce_kernel<<<B_, 256>>>(b2, out);
    aux_kernel<<<1, 1>>>(out, out_size);
}